// round 8
// baseline (speedup 1.0000x reference)
#include <cuda_runtime.h>
#include <cuda_bf16.h>
#include <math.h>
#include <float.h>
#include <stdint.h>

namespace {
constexpr int B_  = 2;
constexpr int S_  = 2048;
constexpr int D_  = 1024;
constexpr int H_  = 16;
constexpr int DH_ = 64;
constexpr int M_  = B_ * S_;          // 4096
constexpr int BH_ = B_ * H_;          // 32
}

// Scratch (device globals — allocation is forbidden)
__device__ float g_qkv[(size_t)M_ * 3 * D_];
__device__ float g_v[(size_t)BH_ * S_ * DH_];

__device__ uint32_t g_Xhi[(size_t)M_ * D_ / 2],  g_Xlo[(size_t)M_ * D_ / 2];
__device__ uint32_t g_W1hi[(size_t)3 * D_ * D_ / 2], g_W1lo[(size_t)3 * D_ * D_ / 2];
__device__ uint32_t g_W2hi[(size_t)D_ * D_ / 2], g_W2lo[(size_t)D_ * D_ / 2];
__device__ uint32_t g_AThi[(size_t)M_ * D_ / 2], g_ATlo[(size_t)M_ * D_ / 2];
__device__ uint32_t g_Qph[(size_t)BH_ * S_ * 32], g_Qpl[(size_t)BH_ * S_ * 32];
__device__ uint32_t g_Kph[(size_t)BH_ * S_ * 32], g_Kpl[(size_t)BH_ * S_ * 32];
__device__ uint32_t g_VTh[(size_t)BH_ * DH_ * (S_ / 2)], g_VTl[(size_t)BH_ * DH_ * (S_ / 2)];

// ---------------------------------------------------------------------------
__device__ __forceinline__ uint32_t smem_u32(const void* p) {
    uint32_t a;
    asm("{ .reg .u64 t; cvta.to.shared.u64 t, %1; cvt.u32.u64 %0, t; }"
        : "=r"(a) : "l"(p));
    return a;
}
__device__ __forceinline__ void split2(float a, float b, uint32_t& h, uint32_t& l)
{
    __nv_bfloat16 ha = __float2bfloat16(a), hb = __float2bfloat16(b);
    float ra = a - __bfloat162float(ha);
    float rb = b - __bfloat162float(hb);
    __nv_bfloat16 la = __float2bfloat16(ra), lb = __float2bfloat16(rb);
    h = ((uint32_t)__bfloat16_as_ushort(hb) << 16) | (uint32_t)__bfloat16_as_ushort(ha);
    l = ((uint32_t)__bfloat16_as_ushort(lb) << 16) | (uint32_t)__bfloat16_as_ushort(la);
}

__global__ void convert_kernel(const float* __restrict__ src,
                               uint32_t* __restrict__ hi,
                               uint32_t* __restrict__ lo, int n4)
{
    int i = blockIdx.x * blockDim.x + threadIdx.x;
    if (i >= n4) return;
    float4 x = reinterpret_cast<const float4*>(src)[i];
    uint2 h, l;
    split2(x.x, x.y, h.x, l.x);
    split2(x.z, x.w, h.y, l.y);
    reinterpret_cast<uint2*>(hi)[i] = h;
    reinterpret_cast<uint2*>(lo)[i] = l;
}

__device__ __forceinline__ void mma_bf16(float c[4], const uint32_t a[4],
                                         uint32_t b0, uint32_t b1)
{
    asm volatile(
        "mma.sync.aligned.m16n8k16.row.col.f32.bf16.bf16.f32 "
        "{%0,%1,%2,%3}, {%4,%5,%6,%7}, {%8,%9}, {%0,%1,%2,%3};"
        : "+f"(c[0]), "+f"(c[1]), "+f"(c[2]), "+f"(c[3])
        : "r"(a[0]), "r"(a[1]), "r"(a[2]), "r"(a[3]), "r"(b0), "r"(b1));
}
__device__ __forceinline__ void ldsm_x4(uint32_t& r0, uint32_t& r1,
                                        uint32_t& r2, uint32_t& r3, uint32_t addr)
{
    asm volatile("ldmatrix.sync.aligned.m8n8.x4.shared.b16 {%0,%1,%2,%3}, [%4];"
                 : "=r"(r0), "=r"(r1), "=r"(r2), "=r"(r3) : "r"(addr));
}
#define CP16(sa, gp) \
    asm volatile("cp.async.cg.shared.global [%0], [%1], 16;" :: "r"(sa), "l"(gp))
#define CP_COMMIT() asm volatile("cp.async.commit_group;" ::: "memory")
#define CP_WAIT(n)  asm volatile("cp.async.wait_group %0;" :: "n"(n) : "memory")

// ---------------------------------------------------------------------------
// GEMM-NT, bf16x3 mma — EXACT R6 config (best measured: 240 us on QKV).
// 2-stage cp.async, chunk = 16 pairs, ldmatrix fragments, PAD=20.
// Dynamic smem: 2 stages x 4 buffers x 128 x 20 u32 = 81920 B.
// ---------------------------------------------------------------------------
__global__ __launch_bounds__(256, 2)
void gemm_mma_kernel(const uint32_t* __restrict__ Ahi, const uint32_t* __restrict__ Alo,
                     const uint32_t* __restrict__ Bhi, const uint32_t* __restrict__ Blo,
                     float* __restrict__ C, int M, int N, int K2)
{
    constexpr int PAD = 20;
    constexpr int BUF = 128 * PAD * 4;
    constexpr int STG = 4 * BUF;
    extern __shared__ uint32_t dsm[];
    const uint32_t sbase = smem_u32(dsm);

    const int tid  = threadIdx.x;
    const int lane = tid & 31;
    const int wid  = tid >> 5;
    const int wm   = wid & 3;
    const int wn   = wid >> 2;
    const int bm   = blockIdx.y * 128;
    const int bn   = blockIdx.x * 128;

    const int cr = tid >> 2;
    const int cj = (tid & 3) << 2;
    const int arow = lane & 15;
    const int asel = ((lane >> 4) << 2);
    const int brow = (lane & 7) + ((lane >> 4) << 3);
    const int bsel = (((lane >> 3) & 1) << 2);

    float c[2][8][4];
#pragma unroll
    for (int mi = 0; mi < 2; mi++)
#pragma unroll
        for (int nj = 0; nj < 8; nj++)
#pragma unroll
            for (int k = 0; k < 4; k++) c[mi][nj][k] = 0.f;

    auto issue = [&](int cc, int stage) {
        const int kp = cc << 4;
        const uint32_t so = sbase + stage * STG;
        const size_t ga0 = (size_t)(bm + cr) * K2 + kp + cj;
        const size_t ga1 = (size_t)(bm + cr + 64) * K2 + kp + cj;
        const size_t gb0 = (size_t)(bn + cr) * K2 + kp + cj;
        const size_t gb1 = (size_t)(bn + cr + 64) * K2 + kp + cj;
        const uint32_t d0 = (uint32_t)(cr * PAD + cj) * 4;
        const uint32_t d1 = (uint32_t)((cr + 64) * PAD + cj) * 4;
        CP16(so + d0,           Ahi + ga0);  CP16(so + d1,           Ahi + ga1);
        CP16(so + BUF + d0,     Alo + ga0);  CP16(so + BUF + d1,     Alo + ga1);
        CP16(so + 2 * BUF + d0, Bhi + gb0);  CP16(so + 2 * BUF + d1, Bhi + gb1);
        CP16(so + 3 * BUF + d0, Blo + gb0);  CP16(so + 3 * BUF + d1, Blo + gb1);
        CP_COMMIT();
    };

    auto compute = [&](int stage) {
        const uint32_t so = sbase + stage * STG;
#pragma unroll
        for (int step = 0; step < 2; step++) {
            const int ko = step << 3;
            uint32_t aH[2][4], aL[2][4];
#pragma unroll
            for (int mi = 0; mi < 2; mi++) {
                const uint32_t ra = so +
                    (uint32_t)((wm * 32 + mi * 16 + arow) * PAD + ko + asel) * 4;
                ldsm_x4(aH[mi][0], aH[mi][1], aH[mi][2], aH[mi][3], ra);
                ldsm_x4(aL[mi][0], aL[mi][1], aL[mi][2], aL[mi][3], ra + BUF);
            }
#pragma unroll
            for (int nj2 = 0; nj2 < 4; nj2++) {
                const uint32_t rb = so + 2 * BUF +
                    (uint32_t)((wn * 64 + nj2 * 16 + brow) * PAD + ko + bsel) * 4;
                uint32_t bh[4], bl[4];
                ldsm_x4(bh[0], bh[1], bh[2], bh[3], rb);
                ldsm_x4(bl[0], bl[1], bl[2], bl[3], rb + BUF);
#pragma unroll
                for (int mi = 0; mi < 2; mi++) {
                    mma_bf16(c[mi][2 * nj2],     aH[mi], bh[0], bh[1]);
                    mma_bf16(c[mi][2 * nj2],     aH[mi], bl[0], bl[1]);
                    mma_bf16(c[mi][2 * nj2],     aL[mi], bh[0], bh[1]);
                    mma_bf16(c[mi][2 * nj2 + 1], aH[mi], bh[2], bh[3]);
                    mma_bf16(c[mi][2 * nj2 + 1], aH[mi], bl[2], bl[3]);
                    mma_bf16(c[mi][2 * nj2 + 1], aL[mi], bh[2], bh[3]);
                }
            }
        }
    };

    const int nchunks = K2 >> 4;
    issue(0, 0);
    for (int cc = 0; cc < nchunks; cc++) {
        if (cc + 1 < nchunks) {
            issue(cc + 1, (cc + 1) & 1);
            CP_WAIT(1);
        } else {
            CP_WAIT(0);
        }
        __syncthreads();
        compute(cc & 1);
        __syncthreads();
    }

    const int g = lane >> 2, t = lane & 3;
#pragma unroll
    for (int mi = 0; mi < 2; mi++) {
        const int row = bm + wm * 32 + mi * 16 + g;
#pragma unroll
        for (int nj = 0; nj < 8; nj++) {
            const int col = bn + wn * 64 + nj * 8 + 2 * t;
            *reinterpret_cast<float2*>(C + (size_t)row * N + col) =
                make_float2(c[mi][nj][0], c[mi][nj][1]);
            *reinterpret_cast<float2*>(C + (size_t)(row + 8) * N + col) =
                make_float2(c[mi][nj][2], c[mi][nj][3]);
        }
    }
}

// ---------------------------------------------------------------------------
// RoPE + split. Packed bf16 hi/lo Q (pre-scaled) and K, fp32 V.
// ---------------------------------------------------------------------------
__global__ void rope_split_kernel()
{
    int idx = blockIdx.x * blockDim.x + threadIdx.x;
    if (idx >= BH_ * S_ * 32) return;
    const int p = idx & 31;
    int t = idx >> 5;
    const int s = t & (S_ - 1);
    t >>= 11;
    const int h = t & (H_ - 1);
    const int b = t >> 4;
    const int bh = b * H_ + h;

    const size_t row = (size_t)(b * S_ + s) * (3 * D_) + h * DH_;
    const float qe = g_qkv[row + 2 * p],          qo = g_qkv[row + 2 * p + 1];
    const float ke = g_qkv[row + D_ + 2 * p],     ko = g_qkv[row + D_ + 2 * p + 1];
    const float ve = g_qkv[row + 2 * D_ + 2 * p], vo = g_qkv[row + 2 * D_ + 2 * p + 1];

    const double invf = exp(-9.210340371976184 * (double)(2 * p) / 64.0);
    const double ang  = (double)s * invf;
    double sd, cd;
    sincos(ang, &sd, &cd);
    const float c = (float)cd, sn = (float)sd;

    const size_t po = ((size_t)bh * S_ + s) * 32 + p;
    uint32_t h32, l32;
    split2(0.125f * (qe * c - qo * sn), 0.125f * (qe * sn + qo * c), h32, l32);
    g_Qph[po] = h32; g_Qpl[po] = l32;
    split2(ke * c - ko * sn, ke * sn + ko * c, h32, l32);
    g_Kph[po] = h32; g_Kpl[po] = l32;

    const size_t vo_ = ((size_t)bh * S_ + s) * DH_ + 2 * p;
    g_v[vo_]     = ve;
    g_v[vo_ + 1] = vo;
}

// ---------------------------------------------------------------------------
// V transpose + bf16 split.
// ---------------------------------------------------------------------------
__global__ __launch_bounds__(256)
void vtrans_kernel()
{
    __shared__ float sv[64][65];
    const int tid = threadIdx.x;
    const int bh  = blockIdx.y;
    const int s0  = blockIdx.x * 64;

    const float* vg = g_v + ((size_t)bh * S_ + s0) * DH_;
#pragma unroll
    for (int i = 0; i < 4; i++) {
        int idx = tid + i * 256;
        int r = idx >> 4, c = (idx & 15) * 4;
        float4 v = *reinterpret_cast<const float4*>(vg + r * DH_ + c);
        sv[r][c] = v.x; sv[r][c + 1] = v.y; sv[r][c + 2] = v.z; sv[r][c + 3] = v.w;
    }
    __syncthreads();
#pragma unroll
    for (int i = 0; i < 8; i++) {
        int o = tid + i * 256;
        int d = o >> 5, sp = o & 31;
        uint32_t h, l;
        split2(sv[2 * sp][d], sv[2 * sp + 1][d], h, l);
        size_t dst = ((size_t)bh * DH_ + d) * (S_ / 2) + (s0 >> 1) + sp;
        g_VTh[dst] = h;
        g_VTl[dst] = l;
    }
}

// ---------------------------------------------------------------------------
// Causal flash attention, bf16x3 mma, 256 threads / 128-query tile.
// 8 warps x 16 q-rows share each 64-key K/V tile (double-buffered cp.async).
// Epilogue writes bf16-split attn directly (feeds the output projection).
// Dynamic smem: 2 stages x 4 buffers x 64 x 36 u32 = 73728 B.
// ---------------------------------------------------------------------------
__global__ __launch_bounds__(256, 2)
void flash_mma_kernel()
{
    constexpr int TBUF = 64 * 36 * 4;
    constexpr int TSTG = 4 * TBUF;
    extern __shared__ uint32_t fsm[];
    const uint32_t sbase = smem_u32(fsm);

    const int tid  = threadIdx.x;
    const int lane = tid & 31;
    const int warp = tid >> 5;          // 0..7
    const int g    = lane >> 2;
    const int t    = lane & 3;
    const int qb   = gridDim.x - 1 - blockIdx.x;   // 0..15, long first
    const int bh   = blockIdx.y;
    const int q0   = qb * 128 + warp * 16;

    const int brow = (lane & 7) + ((lane >> 4) << 3);
    const int bsel = (((lane >> 3) & 1) << 2);

    const uint32_t* kh_g = g_Kph + (size_t)bh * S_ * 32;
    const uint32_t* kl_g = g_Kpl + (size_t)bh * S_ * 32;
    const uint32_t* vh_g = g_VTh + (size_t)bh * DH_ * (S_ / 2);
    const uint32_t* vl_g = g_VTl + (size_t)bh * DH_ * (S_ / 2);

    auto issue = [&](int kb, int stage) {
        const uint32_t so = sbase + stage * TSTG;
        const uint32_t* kh = kh_g + (size_t)(kb * 64) * 32;
        const uint32_t* kl = kl_g + (size_t)(kb * 64) * 32;
        const uint32_t* vh = vh_g + kb * 32;
        const uint32_t* vl = vl_g + kb * 32;
#pragma unroll
        for (int i = 0; i < 2; i++) {
            const int v = tid + i * 256;    // 0..511
            const int r = v >> 3;           // row 0..63
            const int j = (v & 7) * 4;      // word 0..28
            const uint32_t dd = (uint32_t)(r * 36 + j) * 4;
            CP16(so + dd,            kh + r * 32 + j);
            CP16(so + TBUF + dd,     kl + r * 32 + j);
            CP16(so + 2 * TBUF + dd, vh + r * (S_ / 2) + j);
            CP16(so + 3 * TBUF + dd, vl + r * (S_ / 2) + j);
        }
        CP_COMMIT();
    };

    // Q fragments
    uint32_t qh[4][4], ql[4][4];
    {
        const uint32_t* qp = g_Qph + ((size_t)bh * S_ + q0) * 32;
        const uint32_t* qq = g_Qpl + ((size_t)bh * S_ + q0) * 32;
#pragma unroll
        for (int d = 0; d < 4; d++) {
            const int c0 = 8 * d + t;
            qh[d][0] = qp[g * 32 + c0];        qh[d][1] = qp[(g + 8) * 32 + c0];
            qh[d][2] = qp[g * 32 + c0 + 4];    qh[d][3] = qp[(g + 8) * 32 + c0 + 4];
            ql[d][0] = qq[g * 32 + c0];        ql[d][1] = qq[(g + 8) * 32 + c0];
            ql[d][2] = qq[g * 32 + c0 + 4];    ql[d][3] = qq[(g + 8) * 32 + c0 + 4];
        }
    }

    float oc[8][4];
#pragma unroll
    for (int nj = 0; nj < 8; nj++)
#pragma unroll
        for (int k = 0; k < 4; k++) oc[nj][k] = 0.f;
    float m0 = -1e30f, m1 = -1e30f, l0 = 0.f, l1 = 0.f;

    const int kmax = 2 * qb + 1;        // last k-tile index
    issue(0, 0);
    for (int kb = 0; kb <= kmax; kb++) {
        CP_WAIT(0);
        __syncthreads();
        if (kb < kmax) issue(kb + 1, (kb + 1) & 1);

        // Warp entirely above this K tile? (all its rows < kb*64)
        if (kb * 64 > q0 + 15) continue;

        const uint32_t so = sbase + (kb & 1) * TSTG;

        // ---- S = Q K^T ----
        float sc[8][4];
#pragma unroll
        for (int nj = 0; nj < 8; nj++)
#pragma unroll
            for (int k = 0; k < 4; k++) sc[nj][k] = 0.f;

#pragma unroll
        for (int d = 0; d < 4; d++) {
#pragma unroll
            for (int nj2 = 0; nj2 < 4; nj2++) {
                const uint32_t off = so +
                    (uint32_t)((nj2 * 16 + brow) * 36 + 8 * d + bsel) * 4;
                uint32_t kh4[4], kl4[4];
                ldsm_x4(kh4[0], kh4[1], kh4[2], kh4[3], off);
                ldsm_x4(kl4[0], kl4[1], kl4[2], kl4[3], off + TBUF);
                mma_bf16(sc[2 * nj2],     qh[d], kh4[0], kh4[1]);
                mma_bf16(sc[2 * nj2],     qh[d], kl4[0], kl4[1]);
                mma_bf16(sc[2 * nj2],     ql[d], kh4[0], kh4[1]);
                mma_bf16(sc[2 * nj2 + 1], qh[d], kh4[2], kh4[3]);
                mma_bf16(sc[2 * nj2 + 1], qh[d], kl4[2], kl4[3]);
                mma_bf16(sc[2 * nj2 + 1], ql[d], kh4[2], kh4[3]);
            }
        }

        if (kb * 64 + 63 > q0) {        // partial (diagonal) tile: mask
            const int r0 = q0 + g, r1 = r0 + 8;
#pragma unroll
            for (int nj = 0; nj < 8; nj++) {
                const int col = kb * 64 + nj * 8 + 2 * t;
                if (col > r0)     sc[nj][0] = -1e30f;
                if (col + 1 > r0) sc[nj][1] = -1e30f;
                if (col > r1)     sc[nj][2] = -1e30f;
                if (col + 1 > r1) sc[nj][3] = -1e30f;
            }
        }

        // ---- softmax ----
        float rm0 = -1e30f, rm1 = -1e30f;
#pragma unroll
        for (int nj = 0; nj < 8; nj++) {
            rm0 = fmaxf(rm0, fmaxf(sc[nj][0], sc[nj][1]));
            rm1 = fmaxf(rm1, fmaxf(sc[nj][2], sc[nj][3]));
        }
        rm0 = fmaxf(rm0, __shfl_xor_sync(0xffffffffu, rm0, 1));
        rm0 = fmaxf(rm0, __shfl_xor_sync(0xffffffffu, rm0, 2));
        rm1 = fmaxf(rm1, __shfl_xor_sync(0xffffffffu, rm1, 1));
        rm1 = fmaxf(rm1, __shfl_xor_sync(0xffffffffu, rm1, 2));

        const float nm0 = fmaxf(m0, rm0), nm1 = fmaxf(m1, rm1);
        const float corr0 = __expf(m0 - nm0), corr1 = __expf(m1 - nm1);
        m0 = nm0; m1 = nm1;

        float rs0 = 0.f, rs1 = 0.f;
#pragma unroll
        for (int nj = 0; nj < 8; nj++) {
            sc[nj][0] = __expf(sc[nj][0] - m0);
            sc[nj][1] = __expf(sc[nj][1] - m0);
            sc[nj][2] = __expf(sc[nj][2] - m1);
            sc[nj][3] = __expf(sc[nj][3] - m1);
            rs0 += sc[nj][0] + sc[nj][1];
            rs1 += sc[nj][2] + sc[nj][3];
        }
        rs0 += __shfl_xor_sync(0xffffffffu, rs0, 1);
        rs0 += __shfl_xor_sync(0xffffffffu, rs0, 2);
        rs1 += __shfl_xor_sync(0xffffffffu, rs1, 1);
        rs1 += __shfl_xor_sync(0xffffffffu, rs1, 2);
        l0 = l0 * corr0 + rs0;
        l1 = l1 * corr1 + rs1;

#pragma unroll
        for (int nj = 0; nj < 8; nj++) {
            oc[nj][0] *= corr0; oc[nj][1] *= corr0;
            oc[nj][2] *= corr1; oc[nj][3] *= corr1;
        }

        // ---- O += P V ----
#pragma unroll
        for (int s = 0; s < 4; s++) {
            uint32_t ph[4], pl[4];
            split2(sc[2 * s][0],     sc[2 * s][1],     ph[0], pl[0]);
            split2(sc[2 * s][2],     sc[2 * s][3],     ph[1], pl[1]);
            split2(sc[2 * s + 1][0], sc[2 * s + 1][1], ph[2], pl[2]);
            split2(sc[2 * s + 1][2], sc[2 * s + 1][3], ph[3], pl[3]);
#pragma unroll
            for (int nj2 = 0; nj2 < 4; nj2++) {
                const uint32_t off = so + 2 * TBUF +
                    (uint32_t)((nj2 * 16 + brow) * 36 + 8 * s + bsel) * 4;
                uint32_t vh4[4], vl4[4];
                ldsm_x4(vh4[0], vh4[1], vh4[2], vh4[3], off);
                ldsm_x4(vl4[0], vl4[1], vl4[2], vl4[3], off + TBUF);
                mma_bf16(oc[2 * nj2],     ph, vh4[0], vh4[1]);
                mma_bf16(oc[2 * nj2],     ph, vl4[0], vl4[1]);
                mma_bf16(oc[2 * nj2],     pl, vh4[0], vh4[1]);
                mma_bf16(oc[2 * nj2 + 1], ph, vh4[2], vh4[3]);
                mma_bf16(oc[2 * nj2 + 1], ph, vl4[2], vl4[3]);
                mma_bf16(oc[2 * nj2 + 1], pl, vh4[2], vh4[3]);
            }
        }
    }

    // epilogue: normalize + bf16-split directly into the proj gemm operand
    const float inv0 = 1.f / l0, inv1 = 1.f / l1;
    const int b = bh >> 4, h = bh & 15;
    const int r0 = q0 + g, r1 = r0 + 8;
#pragma unroll
    for (int nj = 0; nj < 8; nj++) {
        const size_t p0 = (size_t)(b * S_ + r0) * (D_ / 2) + h * 32 + nj * 4 + t;
        const size_t p1 = (size_t)(b * S_ + r1) * (D_ / 2) + h * 32 + nj * 4 + t;
        uint32_t hh, ll;
        split2(oc[nj][0] * inv0, oc[nj][1] * inv0, hh, ll);
        g_AThi[p0] = hh; g_ATlo[p0] = ll;
        split2(oc[nj][2] * inv1, oc[nj][3] * inv1, hh, ll);
        g_AThi[p1] = hh; g_ATlo[p1] = ll;
    }
}

// ---------------------------------------------------------------------------
extern "C" void kernel_launch(void* const* d_in, const int* in_sizes, int n_in,
                              void* d_out, int out_size)
{
    const float* X    = (const float*)d_in[0];
    const float* Wqkv = (const float*)d_in[1];
    const float* Wo   = (const float*)d_in[2];
    float* out = (float*)d_out;
    (void)in_sizes; (void)n_in; (void)out_size;

    float* qkvp = nullptr;
    cudaGetSymbolAddress((void**)&qkvp, g_qkv);
    uint32_t *xhi, *xlo, *w1hi, *w1lo, *w2hi, *w2lo, *athi, *atlo;
    cudaGetSymbolAddress((void**)&xhi,  g_Xhi);
    cudaGetSymbolAddress((void**)&xlo,  g_Xlo);
    cudaGetSymbolAddress((void**)&w1hi, g_W1hi);
    cudaGetSymbolAddress((void**)&w1lo, g_W1lo);
    cudaGetSymbolAddress((void**)&w2hi, g_W2hi);
    cudaGetSymbolAddress((void**)&w2lo, g_W2lo);
    cudaGetSymbolAddress((void**)&athi, g_AThi);
    cudaGetSymbolAddress((void**)&atlo, g_ATlo);

    const int gemm_smem  = 2 * 4 * 128 * 20 * 4;   // 81920
    const int flash_smem = 2 * 4 * 64 * 36 * 4;    // 73728
    cudaFuncSetAttribute(gemm_mma_kernel,
                         cudaFuncAttributeMaxDynamicSharedMemorySize, gemm_smem);
    cudaFuncSetAttribute(flash_mma_kernel,
                         cudaFuncAttributeMaxDynamicSharedMemorySize, flash_smem);

    // 0) Split inputs into bf16 hi/lo
    {
        int n4 = M_ * D_ / 4;
        convert_kernel<<<n4 / 256, 256>>>(X, xhi, xlo, n4);
        n4 = 3 * D_ * D_ / 4;
        convert_kernel<<<n4 / 256, 256>>>(Wqkv, w1hi, w1lo, n4);
        n4 = D_ * D_ / 4;
        convert_kernel<<<n4 / 256, 256>>>(Wo, w2hi, w2lo, n4);
    }
    // 1) QKV projection
    {
        dim3 grid(3 * D_ / 128, M_ / 128);
        gemm_mma_kernel<<<grid, 256, gemm_smem>>>(xhi, xlo, w1hi, w1lo, qkvp,
                                                  M_, 3 * D_, D_ / 2);
    }
    // 2) RoPE + split
    {
        int total = BH_ * S_ * 32;
        rope_split_kernel<<<total / 256, 256>>>();
    }
    // 2b) V transpose + split
    {
        dim3 grid(S_ / 64, BH_);
        vtrans_kernel<<<grid, 256>>>();
    }
    // 3) Causal flash attention (128-q tiles, fused epilogue split)
    {
        dim3 grid(S_ / 128, BH_);      // (16, 32)
        flash_mma_kernel<<<grid, 256, flash_smem>>>();
    }
    // 4) Output projection (reads the flash-fused split operand)
    {
        dim3 grid(D_ / 128, M_ / 128);
        gemm_mma_kernel<<<grid, 256, gemm_smem>>>(athi, atlo, w2hi, w2lo, out,
                                                  M_, D_, D_ / 2);
    }
}

// round 9
// speedup vs baseline: 1.1929x; 1.1929x over previous
#include <cuda_runtime.h>
#include <cuda_bf16.h>
#include <math.h>
#include <float.h>
#include <stdint.h>

namespace {
constexpr int B_  = 2;
constexpr int S_  = 2048;
constexpr int D_  = 1024;
constexpr int H_  = 16;
constexpr int DH_ = 64;
constexpr int M_  = B_ * S_;          // 4096
constexpr int BH_ = B_ * H_;          // 32
}

// Scratch (device globals — allocation is forbidden)
__device__ float g_qkv[(size_t)M_ * 3 * D_];
__device__ float g_v[(size_t)BH_ * S_ * DH_];

__device__ uint32_t g_Xhi[(size_t)M_ * D_ / 2],  g_Xlo[(size_t)M_ * D_ / 2];
__device__ uint32_t g_W1hi[(size_t)3 * D_ * D_ / 2], g_W1lo[(size_t)3 * D_ * D_ / 2];
__device__ uint32_t g_W2hi[(size_t)D_ * D_ / 2], g_W2lo[(size_t)D_ * D_ / 2];
__device__ uint32_t g_AThi[(size_t)M_ * D_ / 2], g_ATlo[(size_t)M_ * D_ / 2];
__device__ uint32_t g_Qph[(size_t)BH_ * S_ * 32], g_Qpl[(size_t)BH_ * S_ * 32];
__device__ uint32_t g_Kph[(size_t)BH_ * S_ * 32], g_Kpl[(size_t)BH_ * S_ * 32];
__device__ uint32_t g_VTh[(size_t)BH_ * DH_ * (S_ / 2)], g_VTl[(size_t)BH_ * DH_ * (S_ / 2)];

// ---------------------------------------------------------------------------
__device__ __forceinline__ uint32_t smem_u32(const void* p) {
    uint32_t a;
    asm("{ .reg .u64 t; cvta.to.shared.u64 t, %1; cvt.u32.u64 %0, t; }"
        : "=r"(a) : "l"(p));
    return a;
}
__device__ __forceinline__ void split2(float a, float b, uint32_t& h, uint32_t& l)
{
    __nv_bfloat16 ha = __float2bfloat16(a), hb = __float2bfloat16(b);
    float ra = a - __bfloat162float(ha);
    float rb = b - __bfloat162float(hb);
    __nv_bfloat16 la = __float2bfloat16(ra), lb = __float2bfloat16(rb);
    h = ((uint32_t)__bfloat16_as_ushort(hb) << 16) | (uint32_t)__bfloat16_as_ushort(ha);
    l = ((uint32_t)__bfloat16_as_ushort(lb) << 16) | (uint32_t)__bfloat16_as_ushort(la);
}

__global__ void convert_kernel(const float* __restrict__ src,
                               uint32_t* __restrict__ hi,
                               uint32_t* __restrict__ lo, int n4)
{
    int i = blockIdx.x * blockDim.x + threadIdx.x;
    if (i >= n4) return;
    float4 x = reinterpret_cast<const float4*>(src)[i];
    uint2 h, l;
    split2(x.x, x.y, h.x, l.x);
    split2(x.z, x.w, h.y, l.y);
    reinterpret_cast<uint2*>(hi)[i] = h;
    reinterpret_cast<uint2*>(lo)[i] = l;
}

__device__ __forceinline__ void mma_bf16(float c[4], const uint32_t a[4],
                                         uint32_t b0, uint32_t b1)
{
    asm volatile(
        "mma.sync.aligned.m16n8k16.row.col.f32.bf16.bf16.f32 "
        "{%0,%1,%2,%3}, {%4,%5,%6,%7}, {%8,%9}, {%0,%1,%2,%3};"
        : "+f"(c[0]), "+f"(c[1]), "+f"(c[2]), "+f"(c[3])
        : "r"(a[0]), "r"(a[1]), "r"(a[2]), "r"(a[3]), "r"(b0), "r"(b1));
}
__device__ __forceinline__ void ldsm_x4(uint32_t& r0, uint32_t& r1,
                                        uint32_t& r2, uint32_t& r3, uint32_t addr)
{
    asm volatile("ldmatrix.sync.aligned.m8n8.x4.shared.b16 {%0,%1,%2,%3}, [%4];"
                 : "=r"(r0), "=r"(r1), "=r"(r2), "=r"(r3) : "r"(addr));
}
#define CP16(sa, gp) \
    asm volatile("cp.async.cg.shared.global [%0], [%1], 16;" :: "r"(sa), "l"(gp))
#define CP_COMMIT() asm volatile("cp.async.commit_group;" ::: "memory")
#define CP_WAIT(n)  asm volatile("cp.async.wait_group %0;" :: "n"(n) : "memory")

// ---------------------------------------------------------------------------
// GEMM-NT, bf16x3 mma — EXACT R6 config (best measured: 240 us on QKV).
// 2-stage cp.async, chunk = 16 pairs, ldmatrix fragments, PAD=20.
// Dynamic smem: 2 stages x 4 buffers x 128 x 20 u32 = 81920 B.
// ---------------------------------------------------------------------------
__global__ __launch_bounds__(256, 2)
void gemm_mma_kernel(const uint32_t* __restrict__ Ahi, const uint32_t* __restrict__ Alo,
                     const uint32_t* __restrict__ Bhi, const uint32_t* __restrict__ Blo,
                     float* __restrict__ C, int M, int N, int K2)
{
    constexpr int PAD = 20;
    constexpr int BUF = 128 * PAD * 4;
    constexpr int STG = 4 * BUF;
    extern __shared__ uint32_t dsm[];
    const uint32_t sbase = smem_u32(dsm);

    const int tid  = threadIdx.x;
    const int lane = tid & 31;
    const int wid  = tid >> 5;
    const int wm   = wid & 3;
    const int wn   = wid >> 2;
    const int bm   = blockIdx.y * 128;
    const int bn   = blockIdx.x * 128;

    const int cr = tid >> 2;
    const int cj = (tid & 3) << 2;
    const int arow = lane & 15;
    const int asel = ((lane >> 4) << 2);
    const int brow = (lane & 7) + ((lane >> 4) << 3);
    const int bsel = (((lane >> 3) & 1) << 2);

    float c[2][8][4];
#pragma unroll
    for (int mi = 0; mi < 2; mi++)
#pragma unroll
        for (int nj = 0; nj < 8; nj++)
#pragma unroll
            for (int k = 0; k < 4; k++) c[mi][nj][k] = 0.f;

    auto issue = [&](int cc, int stage) {
        const int kp = cc << 4;
        const uint32_t so = sbase + stage * STG;
        const size_t ga0 = (size_t)(bm + cr) * K2 + kp + cj;
        const size_t ga1 = (size_t)(bm + cr + 64) * K2 + kp + cj;
        const size_t gb0 = (size_t)(bn + cr) * K2 + kp + cj;
        const size_t gb1 = (size_t)(bn + cr + 64) * K2 + kp + cj;
        const uint32_t d0 = (uint32_t)(cr * PAD + cj) * 4;
        const uint32_t d1 = (uint32_t)((cr + 64) * PAD + cj) * 4;
        CP16(so + d0,           Ahi + ga0);  CP16(so + d1,           Ahi + ga1);
        CP16(so + BUF + d0,     Alo + ga0);  CP16(so + BUF + d1,     Alo + ga1);
        CP16(so + 2 * BUF + d0, Bhi + gb0);  CP16(so + 2 * BUF + d1, Bhi + gb1);
        CP16(so + 3 * BUF + d0, Blo + gb0);  CP16(so + 3 * BUF + d1, Blo + gb1);
        CP_COMMIT();
    };

    auto compute = [&](int stage) {
        const uint32_t so = sbase + stage * STG;
#pragma unroll
        for (int step = 0; step < 2; step++) {
            const int ko = step << 3;
            uint32_t aH[2][4], aL[2][4];
#pragma unroll
            for (int mi = 0; mi < 2; mi++) {
                const uint32_t ra = so +
                    (uint32_t)((wm * 32 + mi * 16 + arow) * PAD + ko + asel) * 4;
                ldsm_x4(aH[mi][0], aH[mi][1], aH[mi][2], aH[mi][3], ra);
                ldsm_x4(aL[mi][0], aL[mi][1], aL[mi][2], aL[mi][3], ra + BUF);
            }
#pragma unroll
            for (int nj2 = 0; nj2 < 4; nj2++) {
                const uint32_t rb = so + 2 * BUF +
                    (uint32_t)((wn * 64 + nj2 * 16 + brow) * PAD + ko + bsel) * 4;
                uint32_t bh[4], bl[4];
                ldsm_x4(bh[0], bh[1], bh[2], bh[3], rb);
                ldsm_x4(bl[0], bl[1], bl[2], bl[3], rb + BUF);
#pragma unroll
                for (int mi = 0; mi < 2; mi++) {
                    mma_bf16(c[mi][2 * nj2],     aH[mi], bh[0], bh[1]);
                    mma_bf16(c[mi][2 * nj2],     aH[mi], bl[0], bl[1]);
                    mma_bf16(c[mi][2 * nj2],     aL[mi], bh[0], bh[1]);
                    mma_bf16(c[mi][2 * nj2 + 1], aH[mi], bh[2], bh[3]);
                    mma_bf16(c[mi][2 * nj2 + 1], aH[mi], bl[2], bl[3]);
                    mma_bf16(c[mi][2 * nj2 + 1], aL[mi], bh[2], bh[3]);
                }
            }
        }
    };

    const int nchunks = K2 >> 4;
    issue(0, 0);
    for (int cc = 0; cc < nchunks; cc++) {
        if (cc + 1 < nchunks) {
            issue(cc + 1, (cc + 1) & 1);
            CP_WAIT(1);
        } else {
            CP_WAIT(0);
        }
        __syncthreads();
        compute(cc & 1);
        __syncthreads();
    }

    const int g = lane >> 2, t = lane & 3;
#pragma unroll
    for (int mi = 0; mi < 2; mi++) {
        const int row = bm + wm * 32 + mi * 16 + g;
#pragma unroll
        for (int nj = 0; nj < 8; nj++) {
            const int col = bn + wn * 64 + nj * 8 + 2 * t;
            *reinterpret_cast<float2*>(C + (size_t)row * N + col) =
                make_float2(c[mi][nj][0], c[mi][nj][1]);
            *reinterpret_cast<float2*>(C + (size_t)(row + 8) * N + col) =
                make_float2(c[mi][nj][2], c[mi][nj][3]);
        }
    }
}

// ---------------------------------------------------------------------------
// RoPE + split. Packed bf16 hi/lo Q (pre-scaled) and K, fp32 V.
// ---------------------------------------------------------------------------
__global__ void rope_split_kernel()
{
    int idx = blockIdx.x * blockDim.x + threadIdx.x;
    if (idx >= BH_ * S_ * 32) return;
    const int p = idx & 31;
    int t = idx >> 5;
    const int s = t & (S_ - 1);
    t >>= 11;
    const int h = t & (H_ - 1);
    const int b = t >> 4;
    const int bh = b * H_ + h;

    const size_t row = (size_t)(b * S_ + s) * (3 * D_) + h * DH_;
    const float qe = g_qkv[row + 2 * p],          qo = g_qkv[row + 2 * p + 1];
    const float ke = g_qkv[row + D_ + 2 * p],     ko = g_qkv[row + D_ + 2 * p + 1];
    const float ve = g_qkv[row + 2 * D_ + 2 * p], vo = g_qkv[row + 2 * D_ + 2 * p + 1];

    const double invf = exp(-9.210340371976184 * (double)(2 * p) / 64.0);
    const double ang  = (double)s * invf;
    double sd, cd;
    sincos(ang, &sd, &cd);
    const float c = (float)cd, sn = (float)sd;

    const size_t po = ((size_t)bh * S_ + s) * 32 + p;
    uint32_t h32, l32;
    split2(0.125f * (qe * c - qo * sn), 0.125f * (qe * sn + qo * c), h32, l32);
    g_Qph[po] = h32; g_Qpl[po] = l32;
    split2(ke * c - ko * sn, ke * sn + ko * c, h32, l32);
    g_Kph[po] = h32; g_Kpl[po] = l32;

    const size_t vo_ = ((size_t)bh * S_ + s) * DH_ + 2 * p;
    g_v[vo_]     = ve;
    g_v[vo_ + 1] = vo;
}

// ---------------------------------------------------------------------------
// V transpose + bf16 split.
// ---------------------------------------------------------------------------
__global__ __launch_bounds__(256)
void vtrans_kernel()
{
    __shared__ float sv[64][65];
    const int tid = threadIdx.x;
    const int bh  = blockIdx.y;
    const int s0  = blockIdx.x * 64;

    const float* vg = g_v + ((size_t)bh * S_ + s0) * DH_;
#pragma unroll
    for (int i = 0; i < 4; i++) {
        int idx = tid + i * 256;
        int r = idx >> 4, c = (idx & 15) * 4;
        float4 v = *reinterpret_cast<const float4*>(vg + r * DH_ + c);
        sv[r][c] = v.x; sv[r][c + 1] = v.y; sv[r][c + 2] = v.z; sv[r][c + 3] = v.w;
    }
    __syncthreads();
#pragma unroll
    for (int i = 0; i < 8; i++) {
        int o = tid + i * 256;
        int d = o >> 5, sp = o & 31;
        uint32_t h, l;
        split2(sv[2 * sp][d], sv[2 * sp + 1][d], h, l);
        size_t dst = ((size_t)bh * DH_ + d) * (S_ / 2) + (s0 >> 1) + sp;
        g_VTh[dst] = h;
        g_VTl[dst] = l;
    }
}

// ---------------------------------------------------------------------------
// Causal flash attention, bf16x3 mma, 128 threads / 64-query tile,
// double-buffered cp.async staging (R7 layout — no spills), with the
// epilogue writing the bf16-split proj operand directly.
// Dynamic smem: 2 stages x 4 buffers x 64 x 36 u32 = 73728 B.
// ---------------------------------------------------------------------------
__global__ __launch_bounds__(128)
void flash_mma_kernel()
{
    constexpr int TBUF = 64 * 36 * 4;
    constexpr int TSTG = 4 * TBUF;
    extern __shared__ uint32_t fsm[];
    const uint32_t sbase = smem_u32(fsm);

    const int tid  = threadIdx.x;
    const int lane = tid & 31;
    const int warp = tid >> 5;
    const int g    = lane >> 2;
    const int t    = lane & 3;
    const int qb   = gridDim.x - 1 - blockIdx.x;
    const int bh   = blockIdx.y;
    const int q0   = qb * 64 + warp * 16;

    const int brow = (lane & 7) + ((lane >> 4) << 3);
    const int bsel = (((lane >> 3) & 1) << 2);

    const uint32_t* kh_g = g_Kph + (size_t)bh * S_ * 32;
    const uint32_t* kl_g = g_Kpl + (size_t)bh * S_ * 32;
    const uint32_t* vh_g = g_VTh + (size_t)bh * DH_ * (S_ / 2);
    const uint32_t* vl_g = g_VTl + (size_t)bh * DH_ * (S_ / 2);

    auto issue = [&](int kb, int stage) {
        const uint32_t so = sbase + stage * TSTG;
        const uint32_t* kh = kh_g + (size_t)(kb * 64) * 32;
        const uint32_t* kl = kl_g + (size_t)(kb * 64) * 32;
        const uint32_t* vh = vh_g + kb * 32;
        const uint32_t* vl = vl_g + kb * 32;
#pragma unroll
        for (int i = 0; i < 4; i++) {
            const int v = tid + i * 128;
            const int r = v >> 3;
            const int j = (v & 7) * 4;
            const uint32_t dd = (uint32_t)(r * 36 + j) * 4;
            CP16(so + dd,            kh + r * 32 + j);
            CP16(so + TBUF + dd,     kl + r * 32 + j);
            CP16(so + 2 * TBUF + dd, vh + r * (S_ / 2) + j);
            CP16(so + 3 * TBUF + dd, vl + r * (S_ / 2) + j);
        }
        CP_COMMIT();
    };

    // Q fragments
    uint32_t qh[4][4], ql[4][4];
    {
        const uint32_t* qp = g_Qph + ((size_t)bh * S_ + q0) * 32;
        const uint32_t* qq = g_Qpl + ((size_t)bh * S_ + q0) * 32;
#pragma unroll
        for (int d = 0; d < 4; d++) {
            const int c0 = 8 * d + t;
            qh[d][0] = qp[g * 32 + c0];        qh[d][1] = qp[(g + 8) * 32 + c0];
            qh[d][2] = qp[g * 32 + c0 + 4];    qh[d][3] = qp[(g + 8) * 32 + c0 + 4];
            ql[d][0] = qq[g * 32 + c0];        ql[d][1] = qq[(g + 8) * 32 + c0];
            ql[d][2] = qq[g * 32 + c0 + 4];    ql[d][3] = qq[(g + 8) * 32 + c0 + 4];
        }
    }

    float oc[8][4];
#pragma unroll
    for (int nj = 0; nj < 8; nj++)
#pragma unroll
        for (int k = 0; k < 4; k++) oc[nj][k] = 0.f;
    float m0 = -1e30f, m1 = -1e30f, l0 = 0.f, l1 = 0.f;

    issue(0, 0);
    for (int kb = 0; kb <= qb; kb++) {
        CP_WAIT(0);
        __syncthreads();
        if (kb < qb) issue(kb + 1, (kb + 1) & 1);

        const uint32_t so = sbase + (kb & 1) * TSTG;

        // ---- S = Q K^T ----
        float sc[8][4];
#pragma unroll
        for (int nj = 0; nj < 8; nj++)
#pragma unroll
            for (int k = 0; k < 4; k++) sc[nj][k] = 0.f;

#pragma unroll
        for (int d = 0; d < 4; d++) {
#pragma unroll
            for (int nj2 = 0; nj2 < 4; nj2++) {
                const uint32_t off = so +
                    (uint32_t)((nj2 * 16 + brow) * 36 + 8 * d + bsel) * 4;
                uint32_t kh4[4], kl4[4];
                ldsm_x4(kh4[0], kh4[1], kh4[2], kh4[3], off);
                ldsm_x4(kl4[0], kl4[1], kl4[2], kl4[3], off + TBUF);
                mma_bf16(sc[2 * nj2],     qh[d], kh4[0], kh4[1]);
                mma_bf16(sc[2 * nj2],     qh[d], kl4[0], kl4[1]);
                mma_bf16(sc[2 * nj2],     ql[d], kh4[0], kh4[1]);
                mma_bf16(sc[2 * nj2 + 1], qh[d], kh4[2], kh4[3]);
                mma_bf16(sc[2 * nj2 + 1], qh[d], kl4[2], kl4[3]);
                mma_bf16(sc[2 * nj2 + 1], ql[d], kh4[2], kh4[3]);
            }
        }

        if (kb == qb) {
            const int r0 = warp * 16 + g, r1 = r0 + 8;
#pragma unroll
            for (int nj = 0; nj < 8; nj++) {
                const int col = nj * 8 + 2 * t;
                if (col > r0)     sc[nj][0] = -1e30f;
                if (col + 1 > r0) sc[nj][1] = -1e30f;
                if (col > r1)     sc[nj][2] = -1e30f;
                if (col + 1 > r1) sc[nj][3] = -1e30f;
            }
        }

        // ---- softmax ----
        float rm0 = -1e30f, rm1 = -1e30f;
#pragma unroll
        for (int nj = 0; nj < 8; nj++) {
            rm0 = fmaxf(rm0, fmaxf(sc[nj][0], sc[nj][1]));
            rm1 = fmaxf(rm1, fmaxf(sc[nj][2], sc[nj][3]));
        }
        rm0 = fmaxf(rm0, __shfl_xor_sync(0xffffffffu, rm0, 1));
        rm0 = fmaxf(rm0, __shfl_xor_sync(0xffffffffu, rm0, 2));
        rm1 = fmaxf(rm1, __shfl_xor_sync(0xffffffffu, rm1, 1));
        rm1 = fmaxf(rm1, __shfl_xor_sync(0xffffffffu, rm1, 2));

        const float nm0 = fmaxf(m0, rm0), nm1 = fmaxf(m1, rm1);
        const float corr0 = __expf(m0 - nm0), corr1 = __expf(m1 - nm1);
        m0 = nm0; m1 = nm1;

        float rs0 = 0.f, rs1 = 0.f;
#pragma unroll
        for (int nj = 0; nj < 8; nj++) {
            sc[nj][0] = __expf(sc[nj][0] - m0);
            sc[nj][1] = __expf(sc[nj][1] - m0);
            sc[nj][2] = __expf(sc[nj][2] - m1);
            sc[nj][3] = __expf(sc[nj][3] - m1);
            rs0 += sc[nj][0] + sc[nj][1];
            rs1 += sc[nj][2] + sc[nj][3];
        }
        rs0 += __shfl_xor_sync(0xffffffffu, rs0, 1);
        rs0 += __shfl_xor_sync(0xffffffffu, rs0, 2);
        rs1 += __shfl_xor_sync(0xffffffffu, rs1, 1);
        rs1 += __shfl_xor_sync(0xffffffffu, rs1, 2);
        l0 = l0 * corr0 + rs0;
        l1 = l1 * corr1 + rs1;

#pragma unroll
        for (int nj = 0; nj < 8; nj++) {
            oc[nj][0] *= corr0; oc[nj][1] *= corr0;
            oc[nj][2] *= corr1; oc[nj][3] *= corr1;
        }

        // ---- O += P V ----
#pragma unroll
        for (int s = 0; s < 4; s++) {
            uint32_t ph[4], pl[4];
            split2(sc[2 * s][0],     sc[2 * s][1],     ph[0], pl[0]);
            split2(sc[2 * s][2],     sc[2 * s][3],     ph[1], pl[1]);
            split2(sc[2 * s + 1][0], sc[2 * s + 1][1], ph[2], pl[2]);
            split2(sc[2 * s + 1][2], sc[2 * s + 1][3], ph[3], pl[3]);
#pragma unroll
            for (int nj2 = 0; nj2 < 4; nj2++) {
                const uint32_t off = so + 2 * TBUF +
                    (uint32_t)((nj2 * 16 + brow) * 36 + 8 * s + bsel) * 4;
                uint32_t vh4[4], vl4[4];
                ldsm_x4(vh4[0], vh4[1], vh4[2], vh4[3], off);
                ldsm_x4(vl4[0], vl4[1], vl4[2], vl4[3], off + TBUF);
                mma_bf16(oc[2 * nj2],     ph, vh4[0], vh4[1]);
                mma_bf16(oc[2 * nj2],     ph, vl4[0], vl4[1]);
                mma_bf16(oc[2 * nj2],     pl, vh4[0], vh4[1]);
                mma_bf16(oc[2 * nj2 + 1], ph, vh4[2], vh4[3]);
                mma_bf16(oc[2 * nj2 + 1], ph, vl4[2], vl4[3]);
                mma_bf16(oc[2 * nj2 + 1], pl, vh4[2], vh4[3]);
            }
        }
    }

    // epilogue: normalize + bf16-split directly into the proj gemm operand
    const float inv0 = 1.f / l0, inv1 = 1.f / l1;
    const int b = bh >> 4, h = bh & 15;
    const int r0 = q0 + g, r1 = r0 + 8;
#pragma unroll
    for (int nj = 0; nj < 8; nj++) {
        const size_t p0 = (size_t)(b * S_ + r0) * (D_ / 2) + h * 32 + nj * 4 + t;
        const size_t p1 = (size_t)(b * S_ + r1) * (D_ / 2) + h * 32 + nj * 4 + t;
        uint32_t hh, ll;
        split2(oc[nj][0] * inv0, oc[nj][1] * inv0, hh, ll);
        g_AThi[p0] = hh; g_ATlo[p0] = ll;
        split2(oc[nj][2] * inv1, oc[nj][3] * inv1, hh, ll);
        g_AThi[p1] = hh; g_ATlo[p1] = ll;
    }
}

// ---------------------------------------------------------------------------
extern "C" void kernel_launch(void* const* d_in, const int* in_sizes, int n_in,
                              void* d_out, int out_size)
{
    const float* X    = (const float*)d_in[0];
    const float* Wqkv = (const float*)d_in[1];
    const float* Wo   = (const float*)d_in[2];
    float* out = (float*)d_out;
    (void)in_sizes; (void)n_in; (void)out_size;

    float* qkvp = nullptr;
    cudaGetSymbolAddress((void**)&qkvp, g_qkv);
    uint32_t *xhi, *xlo, *w1hi, *w1lo, *w2hi, *w2lo, *athi, *atlo;
    cudaGetSymbolAddress((void**)&xhi,  g_Xhi);
    cudaGetSymbolAddress((void**)&xlo,  g_Xlo);
    cudaGetSymbolAddress((void**)&w1hi, g_W1hi);
    cudaGetSymbolAddress((void**)&w1lo, g_W1lo);
    cudaGetSymbolAddress((void**)&w2hi, g_W2hi);
    cudaGetSymbolAddress((void**)&w2lo, g_W2lo);
    cudaGetSymbolAddress((void**)&athi, g_AThi);
    cudaGetSymbolAddress((void**)&atlo, g_ATlo);

    const int gemm_smem  = 2 * 4 * 128 * 20 * 4;   // 81920
    const int flash_smem = 2 * 4 * 64 * 36 * 4;    // 73728
    cudaFuncSetAttribute(gemm_mma_kernel,
                         cudaFuncAttributeMaxDynamicSharedMemorySize, gemm_smem);
    cudaFuncSetAttribute(flash_mma_kernel,
                         cudaFuncAttributeMaxDynamicSharedMemorySize, flash_smem);

    // 0) Split inputs into bf16 hi/lo
    {
        int n4 = M_ * D_ / 4;
        convert_kernel<<<n4 / 256, 256>>>(X, xhi, xlo, n4);
        n4 = 3 * D_ * D_ / 4;
        convert_kernel<<<n4 / 256, 256>>>(Wqkv, w1hi, w1lo, n4);
        n4 = D_ * D_ / 4;
        convert_kernel<<<n4 / 256, 256>>>(Wo, w2hi, w2lo, n4);
    }
    // 1) QKV projection
    {
        dim3 grid(3 * D_ / 128, M_ / 128);
        gemm_mma_kernel<<<grid, 256, gemm_smem>>>(xhi, xlo, w1hi, w1lo, qkvp,
                                                  M_, 3 * D_, D_ / 2);
    }
    // 2) RoPE + split
    {
        int total = BH_ * S_ * 32;
        rope_split_kernel<<<total / 256, 256>>>();
    }
    // 2b) V transpose + split
    {
        dim3 grid(S_ / 64, BH_);
        vtrans_kernel<<<grid, 256>>>();
    }
    // 3) Causal flash attention (fused epilogue split)
    {
        dim3 grid(S_ / 64, BH_);
        flash_mma_kernel<<<grid, 128, flash_smem>>>();
    }
    // 4) Output projection (reads the flash-fused split operand)
    {
        dim3 grid(D_ / 128, M_ / 128);
        gemm_mma_kernel<<<grid, 256, gemm_smem>>>(athi, atlo, w2hi, w2lo, out,
                                                  M_, D_, D_ / 2);
    }
}

// round 10
// speedup vs baseline: 1.8758x; 1.5724x over previous
#include <cuda_runtime.h>
#include <cuda_bf16.h>
#include <math.h>
#include <float.h>
#include <stdint.h>

namespace {
constexpr int B_  = 2;
constexpr int S_  = 2048;
constexpr int D_  = 1024;
constexpr int H_  = 16;
constexpr int DH_ = 64;
constexpr int M_  = B_ * S_;          // 4096
constexpr int BH_ = B_ * H_;          // 32
}

// Scratch (device globals — allocation is forbidden)
__device__ float g_qkv[(size_t)M_ * 3 * D_];
__device__ float g_v[(size_t)BH_ * S_ * DH_];

__device__ uint32_t g_Xhi[(size_t)M_ * D_ / 2],  g_Xlo[(size_t)M_ * D_ / 2];
__device__ uint32_t g_W1hi[(size_t)3 * D_ * D_ / 2], g_W1lo[(size_t)3 * D_ * D_ / 2];
__device__ uint32_t g_W2hi[(size_t)D_ * D_ / 2], g_W2lo[(size_t)D_ * D_ / 2];
__device__ uint32_t g_AThi[(size_t)M_ * D_ / 2], g_ATlo[(size_t)M_ * D_ / 2];
__device__ uint32_t g_Qph[(size_t)BH_ * S_ * 32], g_Qpl[(size_t)BH_ * S_ * 32];
__device__ uint32_t g_Kph[(size_t)BH_ * S_ * 32], g_Kpl[(size_t)BH_ * S_ * 32];
__device__ uint32_t g_VTh[(size_t)BH_ * DH_ * (S_ / 2)], g_VTl[(size_t)BH_ * DH_ * (S_ / 2)];

// ---------------------------------------------------------------------------
__device__ __forceinline__ uint32_t smem_u32(const void* p) {
    uint32_t a;
    asm("{ .reg .u64 t; cvta.to.shared.u64 t, %1; cvt.u32.u64 %0, t; }"
        : "=r"(a) : "l"(p));
    return a;
}
__device__ __forceinline__ void split2(float a, float b, uint32_t& h, uint32_t& l)
{
    __nv_bfloat16 ha = __float2bfloat16(a), hb = __float2bfloat16(b);
    float ra = a - __bfloat162float(ha);
    float rb = b - __bfloat162float(hb);
    __nv_bfloat16 la = __float2bfloat16(ra), lb = __float2bfloat16(rb);
    h = ((uint32_t)__bfloat16_as_ushort(hb) << 16) | (uint32_t)__bfloat16_as_ushort(ha);
    l = ((uint32_t)__bfloat16_as_ushort(lb) << 16) | (uint32_t)__bfloat16_as_ushort(la);
}

__global__ void convert_kernel(const float* __restrict__ src,
                               uint32_t* __restrict__ hi,
                               uint32_t* __restrict__ lo, int n4)
{
    int i = blockIdx.x * blockDim.x + threadIdx.x;
    if (i >= n4) return;
    float4 x = reinterpret_cast<const float4*>(src)[i];
    uint2 h, l;
    split2(x.x, x.y, h.x, l.x);
    split2(x.z, x.w, h.y, l.y);
    reinterpret_cast<uint2*>(hi)[i] = h;
    reinterpret_cast<uint2*>(lo)[i] = l;
}

__device__ __forceinline__ void mma_bf16(float c[4], const uint32_t a[4],
                                         uint32_t b0, uint32_t b1)
{
    asm volatile(
        "mma.sync.aligned.m16n8k16.row.col.f32.bf16.bf16.f32 "
        "{%0,%1,%2,%3}, {%4,%5,%6,%7}, {%8,%9}, {%0,%1,%2,%3};"
        : "+f"(c[0]), "+f"(c[1]), "+f"(c[2]), "+f"(c[3])
        : "r"(a[0]), "r"(a[1]), "r"(a[2]), "r"(a[3]), "r"(b0), "r"(b1));
}
__device__ __forceinline__ void ldsm_x4(uint32_t& r0, uint32_t& r1,
                                        uint32_t& r2, uint32_t& r3, uint32_t addr)
{
    asm volatile("ldmatrix.sync.aligned.m8n8.x4.shared.b16 {%0,%1,%2,%3}, [%4];"
                 : "=r"(r0), "=r"(r1), "=r"(r2), "=r"(r3) : "r"(addr));
}
#define CP16(sa, gp) \
    asm volatile("cp.async.cg.shared.global [%0], [%1], 16;" :: "r"(sa), "l"(gp))
#define CP_COMMIT() asm volatile("cp.async.commit_group;" ::: "memory")
#define CP_WAIT(n)  asm volatile("cp.async.wait_group %0;" :: "n"(n) : "memory")

// ---------------------------------------------------------------------------
// GEMM-NT, bf16x3 mma. R6 tiling (128x128, 2-stage, chunk=16 pairs, PAD=20),
// but: ONE barrier per chunk, and the 3 split terms interleaved across 4
// independent accumulators (dependency distance 1 -> 4 issues).
// Per-accumulator term order unchanged => bit-identical results.
// ---------------------------------------------------------------------------
__global__ __launch_bounds__(256, 2)
void gemm_mma_kernel(const uint32_t* __restrict__ Ahi, const uint32_t* __restrict__ Alo,
                     const uint32_t* __restrict__ Bhi, const uint32_t* __restrict__ Blo,
                     float* __restrict__ C, int M, int N, int K2)
{
    constexpr int PAD = 20;
    constexpr int BUF = 128 * PAD * 4;
    constexpr int STG = 4 * BUF;
    extern __shared__ uint32_t dsm[];
    const uint32_t sbase = smem_u32(dsm);

    const int tid  = threadIdx.x;
    const int lane = tid & 31;
    const int wid  = tid >> 5;
    const int wm   = wid & 3;
    const int wn   = wid >> 2;
    const int bm   = blockIdx.y * 128;
    const int bn   = blockIdx.x * 128;

    const int cr = tid >> 2;
    const int cj = (tid & 3) << 2;
    const int arow = lane & 15;
    const int asel = ((lane >> 4) << 2);
    const int brow = (lane & 7) + ((lane >> 4) << 3);
    const int bsel = (((lane >> 3) & 1) << 2);

    float c[2][8][4];
#pragma unroll
    for (int mi = 0; mi < 2; mi++)
#pragma unroll
        for (int nj = 0; nj < 8; nj++)
#pragma unroll
            for (int k = 0; k < 4; k++) c[mi][nj][k] = 0.f;

    auto issue = [&](int cc, int stage) {
        const int kp = cc << 4;
        const uint32_t so = sbase + stage * STG;
        const size_t ga0 = (size_t)(bm + cr) * K2 + kp + cj;
        const size_t ga1 = (size_t)(bm + cr + 64) * K2 + kp + cj;
        const size_t gb0 = (size_t)(bn + cr) * K2 + kp + cj;
        const size_t gb1 = (size_t)(bn + cr + 64) * K2 + kp + cj;
        const uint32_t d0 = (uint32_t)(cr * PAD + cj) * 4;
        const uint32_t d1 = (uint32_t)((cr + 64) * PAD + cj) * 4;
        CP16(so + d0,           Ahi + ga0);  CP16(so + d1,           Ahi + ga1);
        CP16(so + BUF + d0,     Alo + ga0);  CP16(so + BUF + d1,     Alo + ga1);
        CP16(so + 2 * BUF + d0, Bhi + gb0);  CP16(so + 2 * BUF + d1, Bhi + gb1);
        CP16(so + 3 * BUF + d0, Blo + gb0);  CP16(so + 3 * BUF + d1, Blo + gb1);
        CP_COMMIT();
    };

    auto compute = [&](int stage) {
        const uint32_t so = sbase + stage * STG;
#pragma unroll
        for (int step = 0; step < 2; step++) {
            const int ko = step << 3;
            uint32_t aH[2][4], aL[2][4];
#pragma unroll
            for (int mi = 0; mi < 2; mi++) {
                const uint32_t ra = so +
                    (uint32_t)((wm * 32 + mi * 16 + arow) * PAD + ko + asel) * 4;
                ldsm_x4(aH[mi][0], aH[mi][1], aH[mi][2], aH[mi][3], ra);
                ldsm_x4(aL[mi][0], aL[mi][1], aL[mi][2], aL[mi][3], ra + BUF);
            }
#pragma unroll
            for (int nj2 = 0; nj2 < 4; nj2++) {
                const uint32_t rb = so + 2 * BUF +
                    (uint32_t)((wn * 64 + nj2 * 16 + brow) * PAD + ko + bsel) * 4;
                uint32_t bh[4], bl[4];
                ldsm_x4(bh[0], bh[1], bh[2], bh[3], rb);
                ldsm_x4(bl[0], bl[1], bl[2], bl[3], rb + BUF);
                // term 1 (hi*hi) across 4 independent accumulators
                mma_bf16(c[0][2 * nj2],     aH[0], bh[0], bh[1]);
                mma_bf16(c[1][2 * nj2],     aH[1], bh[0], bh[1]);
                mma_bf16(c[0][2 * nj2 + 1], aH[0], bh[2], bh[3]);
                mma_bf16(c[1][2 * nj2 + 1], aH[1], bh[2], bh[3]);
                // term 2 (hi*lo)
                mma_bf16(c[0][2 * nj2],     aH[0], bl[0], bl[1]);
                mma_bf16(c[1][2 * nj2],     aH[1], bl[0], bl[1]);
                mma_bf16(c[0][2 * nj2 + 1], aH[0], bl[2], bl[3]);
                mma_bf16(c[1][2 * nj2 + 1], aH[1], bl[2], bl[3]);
                // term 3 (lo*hi)
                mma_bf16(c[0][2 * nj2],     aL[0], bh[0], bh[1]);
                mma_bf16(c[1][2 * nj2],     aL[1], bh[0], bh[1]);
                mma_bf16(c[0][2 * nj2 + 1], aL[0], bh[2], bh[3]);
                mma_bf16(c[1][2 * nj2 + 1], aL[1], bh[2], bh[3]);
            }
        }
    };

    const int nchunks = K2 >> 4;
    issue(0, 0);
    for (int cc = 0; cc < nchunks; cc++) {
        CP_WAIT(0);          // stage cc landed (issued one full chunk ago)
        __syncthreads();     // all warps finished reading the stage we overwrite
        if (cc + 1 < nchunks) issue(cc + 1, (cc + 1) & 1);
        compute(cc & 1);
    }

    const int g = lane >> 2, t = lane & 3;
#pragma unroll
    for (int mi = 0; mi < 2; mi++) {
        const int row = bm + wm * 32 + mi * 16 + g;
#pragma unroll
        for (int nj = 0; nj < 8; nj++) {
            const int col = bn + wn * 64 + nj * 8 + 2 * t;
            *reinterpret_cast<float2*>(C + (size_t)row * N + col) =
                make_float2(c[mi][nj][0], c[mi][nj][1]);
            *reinterpret_cast<float2*>(C + (size_t)(row + 8) * N + col) =
                make_float2(c[mi][nj][2], c[mi][nj][3]);
        }
    }
}

// ---------------------------------------------------------------------------
// RoPE + split. Packed bf16 hi/lo Q (pre-scaled) and K, fp32 V.
// ---------------------------------------------------------------------------
__global__ void rope_split_kernel()
{
    int idx = blockIdx.x * blockDim.x + threadIdx.x;
    if (idx >= BH_ * S_ * 32) return;
    const int p = idx & 31;
    int t = idx >> 5;
    const int s = t & (S_ - 1);
    t >>= 11;
    const int h = t & (H_ - 1);
    const int b = t >> 4;
    const int bh = b * H_ + h;

    const size_t row = (size_t)(b * S_ + s) * (3 * D_) + h * DH_;
    const float qe = g_qkv[row + 2 * p],          qo = g_qkv[row + 2 * p + 1];
    const float ke = g_qkv[row + D_ + 2 * p],     ko = g_qkv[row + D_ + 2 * p + 1];
    const float ve = g_qkv[row + 2 * D_ + 2 * p], vo = g_qkv[row + 2 * D_ + 2 * p + 1];

    const double invf = exp(-9.210340371976184 * (double)(2 * p) / 64.0);
    const double ang  = (double)s * invf;
    double sd, cd;
    sincos(ang, &sd, &cd);
    const float c = (float)cd, sn = (float)sd;

    const size_t po = ((size_t)bh * S_ + s) * 32 + p;
    uint32_t h32, l32;
    split2(0.125f * (qe * c - qo * sn), 0.125f * (qe * sn + qo * c), h32, l32);
    g_Qph[po] = h32; g_Qpl[po] = l32;
    split2(ke * c - ko * sn, ke * sn + ko * c, h32, l32);
    g_Kph[po] = h32; g_Kpl[po] = l32;

    const size_t vo_ = ((size_t)bh * S_ + s) * DH_ + 2 * p;
    g_v[vo_]     = ve;
    g_v[vo_ + 1] = vo;
}

// ---------------------------------------------------------------------------
// V transpose + bf16 split.
// ---------------------------------------------------------------------------
__global__ __launch_bounds__(256)
void vtrans_kernel()
{
    __shared__ float sv[64][65];
    const int tid = threadIdx.x;
    const int bh  = blockIdx.y;
    const int s0  = blockIdx.x * 64;

    const float* vg = g_v + ((size_t)bh * S_ + s0) * DH_;
#pragma unroll
    for (int i = 0; i < 4; i++) {
        int idx = tid + i * 256;
        int r = idx >> 4, c = (idx & 15) * 4;
        float4 v = *reinterpret_cast<const float4*>(vg + r * DH_ + c);
        sv[r][c] = v.x; sv[r][c + 1] = v.y; sv[r][c + 2] = v.z; sv[r][c + 3] = v.w;
    }
    __syncthreads();
#pragma unroll
    for (int i = 0; i < 8; i++) {
        int o = tid + i * 256;
        int d = o >> 5, sp = o & 31;
        uint32_t h, l;
        split2(sv[2 * sp][d], sv[2 * sp + 1][d], h, l);
        size_t dst = ((size_t)bh * DH_ + d) * (S_ / 2) + (s0 >> 1) + sp;
        g_VTh[dst] = h;
        g_VTl[dst] = l;
    }
}

// ---------------------------------------------------------------------------
// Causal flash attention, bf16x3 mma, 128 threads / 64-query tile,
// double-buffered cp.async, fused bf16-split epilogue.
// MMA terms interleaved across the accumulator pair (distance 2).
// ---------------------------------------------------------------------------
__global__ __launch_bounds__(128)
void flash_mma_kernel()
{
    constexpr int TBUF = 64 * 36 * 4;
    constexpr int TSTG = 4 * TBUF;
    extern __shared__ uint32_t fsm[];
    const uint32_t sbase = smem_u32(fsm);

    const int tid  = threadIdx.x;
    const int lane = tid & 31;
    const int warp = tid >> 5;
    const int g    = lane >> 2;
    const int t    = lane & 3;
    const int qb   = gridDim.x - 1 - blockIdx.x;
    const int bh   = blockIdx.y;
    const int q0   = qb * 64 + warp * 16;

    const int brow = (lane & 7) + ((lane >> 4) << 3);
    const int bsel = (((lane >> 3) & 1) << 2);

    const uint32_t* kh_g = g_Kph + (size_t)bh * S_ * 32;
    const uint32_t* kl_g = g_Kpl + (size_t)bh * S_ * 32;
    const uint32_t* vh_g = g_VTh + (size_t)bh * DH_ * (S_ / 2);
    const uint32_t* vl_g = g_VTl + (size_t)bh * DH_ * (S_ / 2);

    auto issue = [&](int kb, int stage) {
        const uint32_t so = sbase + stage * TSTG;
        const uint32_t* kh = kh_g + (size_t)(kb * 64) * 32;
        const uint32_t* kl = kl_g + (size_t)(kb * 64) * 32;
        const uint32_t* vh = vh_g + kb * 32;
        const uint32_t* vl = vl_g + kb * 32;
#pragma unroll
        for (int i = 0; i < 4; i++) {
            const int v = tid + i * 128;
            const int r = v >> 3;
            const int j = (v & 7) * 4;
            const uint32_t dd = (uint32_t)(r * 36 + j) * 4;
            CP16(so + dd,            kh + r * 32 + j);
            CP16(so + TBUF + dd,     kl + r * 32 + j);
            CP16(so + 2 * TBUF + dd, vh + r * (S_ / 2) + j);
            CP16(so + 3 * TBUF + dd, vl + r * (S_ / 2) + j);
        }
        CP_COMMIT();
    };

    // Q fragments
    uint32_t qh[4][4], ql[4][4];
    {
        const uint32_t* qp = g_Qph + ((size_t)bh * S_ + q0) * 32;
        const uint32_t* qq = g_Qpl + ((size_t)bh * S_ + q0) * 32;
#pragma unroll
        for (int d = 0; d < 4; d++) {
            const int c0 = 8 * d + t;
            qh[d][0] = qp[g * 32 + c0];        qh[d][1] = qp[(g + 8) * 32 + c0];
            qh[d][2] = qp[g * 32 + c0 + 4];    qh[d][3] = qp[(g + 8) * 32 + c0 + 4];
            ql[d][0] = qq[g * 32 + c0];        ql[d][1] = qq[(g + 8) * 32 + c0];
            ql[d][2] = qq[g * 32 + c0 + 4];    ql[d][3] = qq[(g + 8) * 32 + c0 + 4];
        }
    }

    float oc[8][4];
#pragma unroll
    for (int nj = 0; nj < 8; nj++)
#pragma unroll
        for (int k = 0; k < 4; k++) oc[nj][k] = 0.f;
    float m0 = -1e30f, m1 = -1e30f, l0 = 0.f, l1 = 0.f;

    issue(0, 0);
    for (int kb = 0; kb <= qb; kb++) {
        CP_WAIT(0);
        __syncthreads();
        if (kb < qb) issue(kb + 1, (kb + 1) & 1);

        const uint32_t so = sbase + (kb & 1) * TSTG;

        // ---- S = Q K^T ----
        float sc[8][4];
#pragma unroll
        for (int nj = 0; nj < 8; nj++)
#pragma unroll
            for (int k = 0; k < 4; k++) sc[nj][k] = 0.f;

#pragma unroll
        for (int d = 0; d < 4; d++) {
#pragma unroll
            for (int nj2 = 0; nj2 < 4; nj2++) {
                const uint32_t off = so +
                    (uint32_t)((nj2 * 16 + brow) * 36 + 8 * d + bsel) * 4;
                uint32_t kh4[4], kl4[4];
                ldsm_x4(kh4[0], kh4[1], kh4[2], kh4[3], off);
                ldsm_x4(kl4[0], kl4[1], kl4[2], kl4[3], off + TBUF);
                mma_bf16(sc[2 * nj2],     qh[d], kh4[0], kh4[1]);
                mma_bf16(sc[2 * nj2 + 1], qh[d], kh4[2], kh4[3]);
                mma_bf16(sc[2 * nj2],     qh[d], kl4[0], kl4[1]);
                mma_bf16(sc[2 * nj2 + 1], qh[d], kl4[2], kl4[3]);
                mma_bf16(sc[2 * nj2],     ql[d], kh4[0], kh4[1]);
                mma_bf16(sc[2 * nj2 + 1], ql[d], kh4[2], kh4[3]);
            }
        }

        if (kb == qb) {
            const int r0 = warp * 16 + g, r1 = r0 + 8;
#pragma unroll
            for (int nj = 0; nj < 8; nj++) {
                const int col = nj * 8 + 2 * t;
                if (col > r0)     sc[nj][0] = -1e30f;
                if (col + 1 > r0) sc[nj][1] = -1e30f;
                if (col > r1)     sc[nj][2] = -1e30f;
                if (col + 1 > r1) sc[nj][3] = -1e30f;
            }
        }

        // ---- softmax ----
        float rm0 = -1e30f, rm1 = -1e30f;
#pragma unroll
        for (int nj = 0; nj < 8; nj++) {
            rm0 = fmaxf(rm0, fmaxf(sc[nj][0], sc[nj][1]));
            rm1 = fmaxf(rm1, fmaxf(sc[nj][2], sc[nj][3]));
        }
        rm0 = fmaxf(rm0, __shfl_xor_sync(0xffffffffu, rm0, 1));
        rm0 = fmaxf(rm0, __shfl_xor_sync(0xffffffffu, rm0, 2));
        rm1 = fmaxf(rm1, __shfl_xor_sync(0xffffffffu, rm1, 1));
        rm1 = fmaxf(rm1, __shfl_xor_sync(0xffffffffu, rm1, 2));

        const float nm0 = fmaxf(m0, rm0), nm1 = fmaxf(m1, rm1);
        const float corr0 = __expf(m0 - nm0), corr1 = __expf(m1 - nm1);
        m0 = nm0; m1 = nm1;

        float rs0 = 0.f, rs1 = 0.f;
#pragma unroll
        for (int nj = 0; nj < 8; nj++) {
            sc[nj][0] = __expf(sc[nj][0] - m0);
            sc[nj][1] = __expf(sc[nj][1] - m0);
            sc[nj][2] = __expf(sc[nj][2] - m1);
            sc[nj][3] = __expf(sc[nj][3] - m1);
            rs0 += sc[nj][0] + sc[nj][1];
            rs1 += sc[nj][2] + sc[nj][3];
        }
        rs0 += __shfl_xor_sync(0xffffffffu, rs0, 1);
        rs0 += __shfl_xor_sync(0xffffffffu, rs0, 2);
        rs1 += __shfl_xor_sync(0xffffffffu, rs1, 1);
        rs1 += __shfl_xor_sync(0xffffffffu, rs1, 2);
        l0 = l0 * corr0 + rs0;
        l1 = l1 * corr1 + rs1;

#pragma unroll
        for (int nj = 0; nj < 8; nj++) {
            oc[nj][0] *= corr0; oc[nj][1] *= corr0;
            oc[nj][2] *= corr1; oc[nj][3] *= corr1;
        }

        // ---- O += P V ----
#pragma unroll
        for (int s = 0; s < 4; s++) {
            uint32_t ph[4], pl[4];
            split2(sc[2 * s][0],     sc[2 * s][1],     ph[0], pl[0]);
            split2(sc[2 * s][2],     sc[2 * s][3],     ph[1], pl[1]);
            split2(sc[2 * s + 1][0], sc[2 * s + 1][1], ph[2], pl[2]);
            split2(sc[2 * s + 1][2], sc[2 * s + 1][3], ph[3], pl[3]);
#pragma unroll
            for (int nj2 = 0; nj2 < 4; nj2++) {
                const uint32_t off = so + 2 * TBUF +
                    (uint32_t)((nj2 * 16 + brow) * 36 + 8 * s + bsel) * 4;
                uint32_t vh4[4], vl4[4];
                ldsm_x4(vh4[0], vh4[1], vh4[2], vh4[3], off);
                ldsm_x4(vl4[0], vl4[1], vl4[2], vl4[3], off + TBUF);
                mma_bf16(oc[2 * nj2],     ph, vh4[0], vh4[1]);
                mma_bf16(oc[2 * nj2 + 1], ph, vh4[2], vh4[3]);
                mma_bf16(oc[2 * nj2],     ph, vl4[0], vl4[1]);
                mma_bf16(oc[2 * nj2 + 1], ph, vl4[2], vl4[3]);
                mma_bf16(oc[2 * nj2],     pl, vh4[0], vh4[1]);
                mma_bf16(oc[2 * nj2 + 1], pl, vh4[2], vh4[3]);
            }
        }
    }

    // epilogue: normalize + bf16-split directly into the proj gemm operand
    const float inv0 = 1.f / l0, inv1 = 1.f / l1;
    const int b = bh >> 4, h = bh & 15;
    const int r0 = q0 + g, r1 = r0 + 8;
#pragma unroll
    for (int nj = 0; nj < 8; nj++) {
        const size_t p0 = (size_t)(b * S_ + r0) * (D_ / 2) + h * 32 + nj * 4 + t;
        const size_t p1 = (size_t)(b * S_ + r1) * (D_ / 2) + h * 32 + nj * 4 + t;
        uint32_t hh, ll;
        split2(oc[nj][0] * inv0, oc[nj][1] * inv0, hh, ll);
        g_AThi[p0] = hh; g_ATlo[p0] = ll;
        split2(oc[nj][2] * inv1, oc[nj][3] * inv1, hh, ll);
        g_AThi[p1] = hh; g_ATlo[p1] = ll;
    }
}

// ---------------------------------------------------------------------------
extern "C" void kernel_launch(void* const* d_in, const int* in_sizes, int n_in,
                              void* d_out, int out_size)
{
    const float* X    = (const float*)d_in[0];
    const float* Wqkv = (const float*)d_in[1];
    const float* Wo   = (const float*)d_in[2];
    float* out = (float*)d_out;
    (void)in_sizes; (void)n_in; (void)out_size;

    float* qkvp = nullptr;
    cudaGetSymbolAddress((void**)&qkvp, g_qkv);
    uint32_t *xhi, *xlo, *w1hi, *w1lo, *w2hi, *w2lo, *athi, *atlo;
    cudaGetSymbolAddress((void**)&xhi,  g_Xhi);
    cudaGetSymbolAddress((void**)&xlo,  g_Xlo);
    cudaGetSymbolAddress((void**)&w1hi, g_W1hi);
    cudaGetSymbolAddress((void**)&w1lo, g_W1lo);
    cudaGetSymbolAddress((void**)&w2hi, g_W2hi);
    cudaGetSymbolAddress((void**)&w2lo, g_W2lo);
    cudaGetSymbolAddress((void**)&athi, g_AThi);
    cudaGetSymbolAddress((void**)&atlo, g_ATlo);

    const int gemm_smem  = 2 * 4 * 128 * 20 * 4;   // 81920
    const int flash_smem = 2 * 4 * 64 * 36 * 4;    // 73728
    cudaFuncSetAttribute(gemm_mma_kernel,
                         cudaFuncAttributeMaxDynamicSharedMemorySize, gemm_smem);
    cudaFuncSetAttribute(flash_mma_kernel,
                         cudaFuncAttributeMaxDynamicSharedMemorySize, flash_smem);

    // 0) Split inputs into bf16 hi/lo
    {
        int n4 = M_ * D_ / 4;
        convert_kernel<<<n4 / 256, 256>>>(X, xhi, xlo, n4);
        n4 = 3 * D_ * D_ / 4;
        convert_kernel<<<n4 / 256, 256>>>(Wqkv, w1hi, w1lo, n4);
        n4 = D_ * D_ / 4;
        convert_kernel<<<n4 / 256, 256>>>(Wo, w2hi, w2lo, n4);
    }
    // 1) QKV projection
    {
        dim3 grid(3 * D_ / 128, M_ / 128);
        gemm_mma_kernel<<<grid, 256, gemm_smem>>>(xhi, xlo, w1hi, w1lo, qkvp,
                                                  M_, 3 * D_, D_ / 2);
    }
    // 2) RoPE + split
    {
        int total = BH_ * S_ * 32;
        rope_split_kernel<<<total / 256, 256>>>();
    }
    // 2b) V transpose + split
    {
        dim3 grid(S_ / 64, BH_);
        vtrans_kernel<<<grid, 256>>>();
    }
    // 3) Causal flash attention (fused epilogue split)
    {
        dim3 grid(S_ / 64, BH_);
        flash_mma_kernel<<<grid, 128, flash_smem>>>();
    }
    // 4) Output projection
    {
        dim3 grid(D_ / 128, M_ / 128);
        gemm_mma_kernel<<<grid, 256, gemm_smem>>>(athi, atlo, w2hi, w2lo, out,
                                                  M_, D_, D_ / 2);
    }
}

// round 11
// speedup vs baseline: 1.8951x; 1.0103x over previous
#include <cuda_runtime.h>
#include <cuda_bf16.h>
#include <math.h>
#include <float.h>
#include <stdint.h>

namespace {
constexpr int B_  = 2;
constexpr int S_  = 2048;
constexpr int D_  = 1024;
constexpr int H_  = 16;
constexpr int DH_ = 64;
constexpr int M_  = B_ * S_;          // 4096
constexpr int BH_ = B_ * H_;          // 32
}

// Scratch (device globals — allocation is forbidden)
__device__ float g_qkv[(size_t)M_ * 3 * D_];
__device__ float g_v[(size_t)BH_ * S_ * DH_];

__device__ uint32_t g_Xhi[(size_t)M_ * D_ / 2],  g_Xlo[(size_t)M_ * D_ / 2];
__device__ uint32_t g_W1hi[(size_t)3 * D_ * D_ / 2], g_W1lo[(size_t)3 * D_ * D_ / 2];
__device__ uint32_t g_W2hi[(size_t)D_ * D_ / 2], g_W2lo[(size_t)D_ * D_ / 2];
__device__ uint32_t g_AThi[(size_t)M_ * D_ / 2], g_ATlo[(size_t)M_ * D_ / 2];
__device__ uint32_t g_Qph[(size_t)BH_ * S_ * 32], g_Qpl[(size_t)BH_ * S_ * 32];
__device__ uint32_t g_Kph[(size_t)BH_ * S_ * 32], g_Kpl[(size_t)BH_ * S_ * 32];
__device__ uint32_t g_VTh[(size_t)BH_ * DH_ * (S_ / 2)], g_VTl[(size_t)BH_ * DH_ * (S_ / 2)];

// ---------------------------------------------------------------------------
__device__ __forceinline__ uint32_t smem_u32(const void* p) {
    uint32_t a;
    asm("{ .reg .u64 t; cvta.to.shared.u64 t, %1; cvt.u32.u64 %0, t; }"
        : "=r"(a) : "l"(p));
    return a;
}
// bf16 hi/lo split of a float pair; bit-identical to the __float2bfloat16
// version but ~6 ops via packed cvt.
__device__ __forceinline__ void split2(float a, float b, uint32_t& h, uint32_t& l)
{
    asm("cvt.rn.bf16x2.f32 %0, %1, %2;" : "=r"(h) : "f"(b), "f"(a));
    const float ha = __uint_as_float(h << 16);
    const float hb = __uint_as_float(h & 0xFFFF0000u);
    const float la = a - ha, lb = b - hb;
    asm("cvt.rn.bf16x2.f32 %0, %1, %2;" : "=r"(l) : "f"(lb), "f"(la));
}
__device__ __forceinline__ float ex2f(float x) {
    float y;
    asm("ex2.approx.f32 %0, %1;" : "=f"(y) : "f"(x));
    return y;
}

__global__ void convert_kernel(const float* __restrict__ src,
                               uint32_t* __restrict__ hi,
                               uint32_t* __restrict__ lo, int n4)
{
    int i = blockIdx.x * blockDim.x + threadIdx.x;
    if (i >= n4) return;
    float4 x = reinterpret_cast<const float4*>(src)[i];
    uint2 h, l;
    split2(x.x, x.y, h.x, l.x);
    split2(x.z, x.w, h.y, l.y);
    reinterpret_cast<uint2*>(hi)[i] = h;
    reinterpret_cast<uint2*>(lo)[i] = l;
}

__device__ __forceinline__ void mma_bf16(float c[4], const uint32_t a[4],
                                         uint32_t b0, uint32_t b1)
{
    asm volatile(
        "mma.sync.aligned.m16n8k16.row.col.f32.bf16.bf16.f32 "
        "{%0,%1,%2,%3}, {%4,%5,%6,%7}, {%8,%9}, {%0,%1,%2,%3};"
        : "+f"(c[0]), "+f"(c[1]), "+f"(c[2]), "+f"(c[3])
        : "r"(a[0]), "r"(a[1]), "r"(a[2]), "r"(a[3]), "r"(b0), "r"(b1));
}
__device__ __forceinline__ void ldsm_x4(uint32_t& r0, uint32_t& r1,
                                        uint32_t& r2, uint32_t& r3, uint32_t addr)
{
    asm volatile("ldmatrix.sync.aligned.m8n8.x4.shared.b16 {%0,%1,%2,%3}, [%4];"
                 : "=r"(r0), "=r"(r1), "=r"(r2), "=r"(r3) : "r"(addr));
}
#define CP16(sa, gp) \
    asm volatile("cp.async.cg.shared.global [%0], [%1], 16;" :: "r"(sa), "l"(gp))
#define CP_COMMIT() asm volatile("cp.async.commit_group;" ::: "memory")
#define CP_WAIT(n)  asm volatile("cp.async.wait_group %0;" :: "n"(n) : "memory")

// ---------------------------------------------------------------------------
// GEMM-NT, bf16x3 mma (R10 config — best measured).
// ---------------------------------------------------------------------------
__global__ __launch_bounds__(256, 2)
void gemm_mma_kernel(const uint32_t* __restrict__ Ahi, const uint32_t* __restrict__ Alo,
                     const uint32_t* __restrict__ Bhi, const uint32_t* __restrict__ Blo,
                     float* __restrict__ C, int M, int N, int K2)
{
    constexpr int PAD = 20;
    constexpr int BUF = 128 * PAD * 4;
    constexpr int STG = 4 * BUF;
    extern __shared__ uint32_t dsm[];
    const uint32_t sbase = smem_u32(dsm);

    const int tid  = threadIdx.x;
    const int lane = tid & 31;
    const int wid  = tid >> 5;
    const int wm   = wid & 3;
    const int wn   = wid >> 2;
    const int bm   = blockIdx.y * 128;
    const int bn   = blockIdx.x * 128;

    const int cr = tid >> 2;
    const int cj = (tid & 3) << 2;
    const int arow = lane & 15;
    const int asel = ((lane >> 4) << 2);
    const int brow = (lane & 7) + ((lane >> 4) << 3);
    const int bsel = (((lane >> 3) & 1) << 2);

    float c[2][8][4];
#pragma unroll
    for (int mi = 0; mi < 2; mi++)
#pragma unroll
        for (int nj = 0; nj < 8; nj++)
#pragma unroll
            for (int k = 0; k < 4; k++) c[mi][nj][k] = 0.f;

    auto issue = [&](int cc, int stage) {
        const int kp = cc << 4;
        const uint32_t so = sbase + stage * STG;
        const size_t ga0 = (size_t)(bm + cr) * K2 + kp + cj;
        const size_t ga1 = (size_t)(bm + cr + 64) * K2 + kp + cj;
        const size_t gb0 = (size_t)(bn + cr) * K2 + kp + cj;
        const size_t gb1 = (size_t)(bn + cr + 64) * K2 + kp + cj;
        const uint32_t d0 = (uint32_t)(cr * PAD + cj) * 4;
        const uint32_t d1 = (uint32_t)((cr + 64) * PAD + cj) * 4;
        CP16(so + d0,           Ahi + ga0);  CP16(so + d1,           Ahi + ga1);
        CP16(so + BUF + d0,     Alo + ga0);  CP16(so + BUF + d1,     Alo + ga1);
        CP16(so + 2 * BUF + d0, Bhi + gb0);  CP16(so + 2 * BUF + d1, Bhi + gb1);
        CP16(so + 3 * BUF + d0, Blo + gb0);  CP16(so + 3 * BUF + d1, Blo + gb1);
        CP_COMMIT();
    };

    auto compute = [&](int stage) {
        const uint32_t so = sbase + stage * STG;
#pragma unroll
        for (int step = 0; step < 2; step++) {
            const int ko = step << 3;
            uint32_t aH[2][4], aL[2][4];
#pragma unroll
            for (int mi = 0; mi < 2; mi++) {
                const uint32_t ra = so +
                    (uint32_t)((wm * 32 + mi * 16 + arow) * PAD + ko + asel) * 4;
                ldsm_x4(aH[mi][0], aH[mi][1], aH[mi][2], aH[mi][3], ra);
                ldsm_x4(aL[mi][0], aL[mi][1], aL[mi][2], aL[mi][3], ra + BUF);
            }
#pragma unroll
            for (int nj2 = 0; nj2 < 4; nj2++) {
                const uint32_t rb = so + 2 * BUF +
                    (uint32_t)((wn * 64 + nj2 * 16 + brow) * PAD + ko + bsel) * 4;
                uint32_t bh[4], bl[4];
                ldsm_x4(bh[0], bh[1], bh[2], bh[3], rb);
                ldsm_x4(bl[0], bl[1], bl[2], bl[3], rb + BUF);
                mma_bf16(c[0][2 * nj2],     aH[0], bh[0], bh[1]);
                mma_bf16(c[1][2 * nj2],     aH[1], bh[0], bh[1]);
                mma_bf16(c[0][2 * nj2 + 1], aH[0], bh[2], bh[3]);
                mma_bf16(c[1][2 * nj2 + 1], aH[1], bh[2], bh[3]);
                mma_bf16(c[0][2 * nj2],     aH[0], bl[0], bl[1]);
                mma_bf16(c[1][2 * nj2],     aH[1], bl[0], bl[1]);
                mma_bf16(c[0][2 * nj2 + 1], aH[0], bl[2], bl[3]);
                mma_bf16(c[1][2 * nj2 + 1], aH[1], bl[2], bl[3]);
                mma_bf16(c[0][2 * nj2],     aL[0], bh[0], bh[1]);
                mma_bf16(c[1][2 * nj2],     aL[1], bh[0], bh[1]);
                mma_bf16(c[0][2 * nj2 + 1], aL[0], bh[2], bh[3]);
                mma_bf16(c[1][2 * nj2 + 1], aL[1], bh[2], bh[3]);
            }
        }
    };

    const int nchunks = K2 >> 4;
    issue(0, 0);
    for (int cc = 0; cc < nchunks; cc++) {
        CP_WAIT(0);
        __syncthreads();
        if (cc + 1 < nchunks) issue(cc + 1, (cc + 1) & 1);
        compute(cc & 1);
    }

    const int g = lane >> 2, t = lane & 3;
#pragma unroll
    for (int mi = 0; mi < 2; mi++) {
        const int row = bm + wm * 32 + mi * 16 + g;
#pragma unroll
        for (int nj = 0; nj < 8; nj++) {
            const int col = bn + wn * 64 + nj * 8 + 2 * t;
            *reinterpret_cast<float2*>(C + (size_t)row * N + col) =
                make_float2(c[mi][nj][0], c[mi][nj][1]);
            *reinterpret_cast<float2*>(C + (size_t)(row + 8) * N + col) =
                make_float2(c[mi][nj][2], c[mi][nj][3]);
        }
    }
}

// ---------------------------------------------------------------------------
// RoPE + split. Q pre-scaled by 0.125*log2(e) (flash works in exp2 domain).
// ---------------------------------------------------------------------------
__global__ void rope_split_kernel()
{
    int idx = blockIdx.x * blockDim.x + threadIdx.x;
    if (idx >= BH_ * S_ * 32) return;
    const int p = idx & 31;
    int t = idx >> 5;
    const int s = t & (S_ - 1);
    t >>= 11;
    const int h = t & (H_ - 1);
    const int b = t >> 4;
    const int bh = b * H_ + h;

    const size_t row = (size_t)(b * S_ + s) * (3 * D_) + h * DH_;
    const float qe = g_qkv[row + 2 * p],          qo = g_qkv[row + 2 * p + 1];
    const float ke = g_qkv[row + D_ + 2 * p],     ko = g_qkv[row + D_ + 2 * p + 1];
    const float ve = g_qkv[row + 2 * D_ + 2 * p], vo = g_qkv[row + 2 * D_ + 2 * p + 1];

    const double invf = exp(-9.210340371976184 * (double)(2 * p) / 64.0);
    const double ang  = (double)s * invf;
    double sd, cd;
    sincos(ang, &sd, &cd);
    const float c = (float)cd, sn = (float)sd;

    const float QSCALE = 0.18033688011112042f;   // 0.125 * log2(e)
    const size_t po = ((size_t)bh * S_ + s) * 32 + p;
    uint32_t h32, l32;
    split2(QSCALE * (qe * c - qo * sn), QSCALE * (qe * sn + qo * c), h32, l32);
    g_Qph[po] = h32; g_Qpl[po] = l32;
    split2(ke * c - ko * sn, ke * sn + ko * c, h32, l32);
    g_Kph[po] = h32; g_Kpl[po] = l32;

    const size_t vo_ = ((size_t)bh * S_ + s) * DH_ + 2 * p;
    g_v[vo_]     = ve;
    g_v[vo_ + 1] = vo;
}

// ---------------------------------------------------------------------------
// V transpose + bf16 split.
// ---------------------------------------------------------------------------
__global__ __launch_bounds__(256)
void vtrans_kernel()
{
    __shared__ float sv[64][65];
    const int tid = threadIdx.x;
    const int bh  = blockIdx.y;
    const int s0  = blockIdx.x * 64;

    const float* vg = g_v + ((size_t)bh * S_ + s0) * DH_;
#pragma unroll
    for (int i = 0; i < 4; i++) {
        int idx = tid + i * 256;
        int r = idx >> 4, c = (idx & 15) * 4;
        float4 v = *reinterpret_cast<const float4*>(vg + r * DH_ + c);
        sv[r][c] = v.x; sv[r][c + 1] = v.y; sv[r][c + 2] = v.z; sv[r][c + 3] = v.w;
    }
    __syncthreads();
#pragma unroll
    for (int i = 0; i < 8; i++) {
        int o = tid + i * 256;
        int d = o >> 5, sp = o & 31;
        uint32_t h, l;
        split2(sv[2 * sp][d], sv[2 * sp + 1][d], h, l);
        size_t dst = ((size_t)bh * DH_ + d) * (S_ / 2) + (s0 >> 1) + sp;
        g_VTh[dst] = h;
        g_VTl[dst] = l;
    }
}

// ---------------------------------------------------------------------------
// Causal flash attention, bf16x3 mma, exp2-domain softmax, deferred l
// reduction, fused bf16-split epilogue.
// ---------------------------------------------------------------------------
__global__ __launch_bounds__(128)
void flash_mma_kernel()
{
    constexpr int TBUF = 64 * 36 * 4;
    constexpr int TSTG = 4 * TBUF;
    extern __shared__ uint32_t fsm[];
    const uint32_t sbase = smem_u32(fsm);

    const int tid  = threadIdx.x;
    const int lane = tid & 31;
    const int warp = tid >> 5;
    const int g    = lane >> 2;
    const int t    = lane & 3;
    const int qb   = gridDim.x - 1 - blockIdx.x;
    const int bh   = blockIdx.y;
    const int q0   = qb * 64 + warp * 16;

    const int brow = (lane & 7) + ((lane >> 4) << 3);
    const int bsel = (((lane >> 3) & 1) << 2);

    const uint32_t* kh_g = g_Kph + (size_t)bh * S_ * 32;
    const uint32_t* kl_g = g_Kpl + (size_t)bh * S_ * 32;
    const uint32_t* vh_g = g_VTh + (size_t)bh * DH_ * (S_ / 2);
    const uint32_t* vl_g = g_VTl + (size_t)bh * DH_ * (S_ / 2);

    auto issue = [&](int kb, int stage) {
        const uint32_t so = sbase + stage * TSTG;
        const uint32_t* kh = kh_g + (size_t)(kb * 64) * 32;
        const uint32_t* kl = kl_g + (size_t)(kb * 64) * 32;
        const uint32_t* vh = vh_g + kb * 32;
        const uint32_t* vl = vl_g + kb * 32;
#pragma unroll
        for (int i = 0; i < 4; i++) {
            const int v = tid + i * 128;
            const int r = v >> 3;
            const int j = (v & 7) * 4;
            const uint32_t dd = (uint32_t)(r * 36 + j) * 4;
            CP16(so + dd,            kh + r * 32 + j);
            CP16(so + TBUF + dd,     kl + r * 32 + j);
            CP16(so + 2 * TBUF + dd, vh + r * (S_ / 2) + j);
            CP16(so + 3 * TBUF + dd, vl + r * (S_ / 2) + j);
        }
        CP_COMMIT();
    };

    // Q fragments
    uint32_t qh[4][4], ql[4][4];
    {
        const uint32_t* qp = g_Qph + ((size_t)bh * S_ + q0) * 32;
        const uint32_t* qq = g_Qpl + ((size_t)bh * S_ + q0) * 32;
#pragma unroll
        for (int d = 0; d < 4; d++) {
            const int c0 = 8 * d + t;
            qh[d][0] = qp[g * 32 + c0];        qh[d][1] = qp[(g + 8) * 32 + c0];
            qh[d][2] = qp[g * 32 + c0 + 4];    qh[d][3] = qp[(g + 8) * 32 + c0 + 4];
            ql[d][0] = qq[g * 32 + c0];        ql[d][1] = qq[(g + 8) * 32 + c0];
            ql[d][2] = qq[g * 32 + c0 + 4];    ql[d][3] = qq[(g + 8) * 32 + c0 + 4];
        }
    }

    float oc[8][4];
#pragma unroll
    for (int nj = 0; nj < 8; nj++)
#pragma unroll
        for (int k = 0; k < 4; k++) oc[nj][k] = 0.f;
    float m0 = -1e30f, m1 = -1e30f, l0 = 0.f, l1 = 0.f;   // l: per-thread partials

    issue(0, 0);
    for (int kb = 0; kb <= qb; kb++) {
        CP_WAIT(0);
        __syncthreads();
        if (kb < qb) issue(kb + 1, (kb + 1) & 1);

        const uint32_t so = sbase + (kb & 1) * TSTG;

        // ---- S = Q K^T  (scores already in log2 domain via Q scale) ----
        float sc[8][4];
#pragma unroll
        for (int nj = 0; nj < 8; nj++)
#pragma unroll
            for (int k = 0; k < 4; k++) sc[nj][k] = 0.f;

#pragma unroll
        for (int d = 0; d < 4; d++) {
#pragma unroll
            for (int nj2 = 0; nj2 < 4; nj2++) {
                const uint32_t off = so +
                    (uint32_t)((nj2 * 16 + brow) * 36 + 8 * d + bsel) * 4;
                uint32_t kh4[4], kl4[4];
                ldsm_x4(kh4[0], kh4[1], kh4[2], kh4[3], off);
                ldsm_x4(kl4[0], kl4[1], kl4[2], kl4[3], off + TBUF);
                mma_bf16(sc[2 * nj2],     qh[d], kh4[0], kh4[1]);
                mma_bf16(sc[2 * nj2 + 1], qh[d], kh4[2], kh4[3]);
                mma_bf16(sc[2 * nj2],     qh[d], kl4[0], kl4[1]);
                mma_bf16(sc[2 * nj2 + 1], qh[d], kl4[2], kl4[3]);
                mma_bf16(sc[2 * nj2],     ql[d], kh4[0], kh4[1]);
                mma_bf16(sc[2 * nj2 + 1], ql[d], kh4[2], kh4[3]);
            }
        }

        if (kb == qb) {
            const int r0 = warp * 16 + g, r1 = r0 + 8;
#pragma unroll
            for (int nj = 0; nj < 8; nj++) {
                const int col = nj * 8 + 2 * t;
                if (col > r0)     sc[nj][0] = -1e30f;
                if (col + 1 > r0) sc[nj][1] = -1e30f;
                if (col > r1)     sc[nj][2] = -1e30f;
                if (col + 1 > r1) sc[nj][3] = -1e30f;
            }
        }

        // ---- softmax (exp2 domain) ----
        float rm0 = -1e30f, rm1 = -1e30f;
#pragma unroll
        for (int nj = 0; nj < 8; nj++) {
            rm0 = fmaxf(rm0, fmaxf(sc[nj][0], sc[nj][1]));
            rm1 = fmaxf(rm1, fmaxf(sc[nj][2], sc[nj][3]));
        }
        rm0 = fmaxf(rm0, __shfl_xor_sync(0xffffffffu, rm0, 1));
        rm0 = fmaxf(rm0, __shfl_xor_sync(0xffffffffu, rm0, 2));
        rm1 = fmaxf(rm1, __shfl_xor_sync(0xffffffffu, rm1, 1));
        rm1 = fmaxf(rm1, __shfl_xor_sync(0xffffffffu, rm1, 2));

        const float nm0 = fmaxf(m0, rm0), nm1 = fmaxf(m1, rm1);
        const float corr0 = ex2f(m0 - nm0), corr1 = ex2f(m1 - nm1);
        m0 = nm0; m1 = nm1;

        float rs0 = 0.f, rs1 = 0.f;
#pragma unroll
        for (int nj = 0; nj < 8; nj++) {
            sc[nj][0] = ex2f(sc[nj][0] - m0);
            sc[nj][1] = ex2f(sc[nj][1] - m0);
            sc[nj][2] = ex2f(sc[nj][2] - m1);
            sc[nj][3] = ex2f(sc[nj][3] - m1);
            rs0 += sc[nj][0] + sc[nj][1];
            rs1 += sc[nj][2] + sc[nj][3];
        }
        l0 = l0 * corr0 + rs0;        // per-thread partial; reduced in epilogue
        l1 = l1 * corr1 + rs1;

#pragma unroll
        for (int nj = 0; nj < 8; nj++) {
            oc[nj][0] *= corr0; oc[nj][1] *= corr0;
            oc[nj][2] *= corr1; oc[nj][3] *= corr1;
        }

        // ---- O += P V ----
#pragma unroll
        for (int s = 0; s < 4; s++) {
            uint32_t ph[4], pl[4];
            split2(sc[2 * s][0],     sc[2 * s][1],     ph[0], pl[0]);
            split2(sc[2 * s][2],     sc[2 * s][3],     ph[1], pl[1]);
            split2(sc[2 * s + 1][0], sc[2 * s + 1][1], ph[2], pl[2]);
            split2(sc[2 * s + 1][2], sc[2 * s + 1][3], ph[3], pl[3]);
#pragma unroll
            for (int nj2 = 0; nj2 < 4; nj2++) {
                const uint32_t off = so + 2 * TBUF +
                    (uint32_t)((nj2 * 16 + brow) * 36 + 8 * s + bsel) * 4;
                uint32_t vh4[4], vl4[4];
                ldsm_x4(vh4[0], vh4[1], vh4[2], vh4[3], off);
                ldsm_x4(vl4[0], vl4[1], vl4[2], vl4[3], off + TBUF);
                mma_bf16(oc[2 * nj2],     ph, vh4[0], vh4[1]);
                mma_bf16(oc[2 * nj2 + 1], ph, vh4[2], vh4[3]);
                mma_bf16(oc[2 * nj2],     ph, vl4[0], vl4[1]);
                mma_bf16(oc[2 * nj2 + 1], ph, vl4[2], vl4[3]);
                mma_bf16(oc[2 * nj2],     pl, vh4[0], vh4[1]);
                mma_bf16(oc[2 * nj2 + 1], pl, vh4[2], vh4[3]);
            }
        }
    }

    // epilogue: reduce l across the quad, normalize, bf16-split to operand
    l0 += __shfl_xor_sync(0xffffffffu, l0, 1);
    l0 += __shfl_xor_sync(0xffffffffu, l0, 2);
    l1 += __shfl_xor_sync(0xffffffffu, l1, 1);
    l1 += __shfl_xor_sync(0xffffffffu, l1, 2);
    const float inv0 = 1.f / l0, inv1 = 1.f / l1;
    const int b = bh >> 4, h = bh & 15;
    const int r0 = q0 + g, r1 = r0 + 8;
#pragma unroll
    for (int nj = 0; nj < 8; nj++) {
        const size_t p0 = (size_t)(b * S_ + r0) * (D_ / 2) + h * 32 + nj * 4 + t;
        const size_t p1 = (size_t)(b * S_ + r1) * (D_ / 2) + h * 32 + nj * 4 + t;
        uint32_t hh, ll;
        split2(oc[nj][0] * inv0, oc[nj][1] * inv0, hh, ll);
        g_AThi[p0] = hh; g_ATlo[p0] = ll;
        split2(oc[nj][2] * inv1, oc[nj][3] * inv1, hh, ll);
        g_AThi[p1] = hh; g_ATlo[p1] = ll;
    }
}

// ---------------------------------------------------------------------------
extern "C" void kernel_launch(void* const* d_in, const int* in_sizes, int n_in,
                              void* d_out, int out_size)
{
    const float* X    = (const float*)d_in[0];
    const float* Wqkv = (const float*)d_in[1];
    const float* Wo   = (const float*)d_in[2];
    float* out = (float*)d_out;
    (void)in_sizes; (void)n_in; (void)out_size;

    float* qkvp = nullptr;
    cudaGetSymbolAddress((void**)&qkvp, g_qkv);
    uint32_t *xhi, *xlo, *w1hi, *w1lo, *w2hi, *w2lo, *athi, *atlo;
    cudaGetSymbolAddress((void**)&xhi,  g_Xhi);
    cudaGetSymbolAddress((void**)&xlo,  g_Xlo);
    cudaGetSymbolAddress((void**)&w1hi, g_W1hi);
    cudaGetSymbolAddress((void**)&w1lo, g_W1lo);
    cudaGetSymbolAddress((void**)&w2hi, g_W2hi);
    cudaGetSymbolAddress((void**)&w2lo, g_W2lo);
    cudaGetSymbolAddress((void**)&athi, g_AThi);
    cudaGetSymbolAddress((void**)&atlo, g_ATlo);

    const int gemm_smem  = 2 * 4 * 128 * 20 * 4;   // 81920
    const int flash_smem = 2 * 4 * 64 * 36 * 4;    // 73728
    cudaFuncSetAttribute(gemm_mma_kernel,
                         cudaFuncAttributeMaxDynamicSharedMemorySize, gemm_smem);
    cudaFuncSetAttribute(flash_mma_kernel,
                         cudaFuncAttributeMaxDynamicSharedMemorySize, flash_smem);

    // 0) Split inputs into bf16 hi/lo
    {
        int n4 = M_ * D_ / 4;
        convert_kernel<<<n4 / 256, 256>>>(X, xhi, xlo, n4);
        n4 = 3 * D_ * D_ / 4;
        convert_kernel<<<n4 / 256, 256>>>(Wqkv, w1hi, w1lo, n4);
        n4 = D_ * D_ / 4;
        convert_kernel<<<n4 / 256, 256>>>(Wo, w2hi, w2lo, n4);
    }
    // 1) QKV projection
    {
        dim3 grid(3 * D_ / 128, M_ / 128);
        gemm_mma_kernel<<<grid, 256, gemm_smem>>>(xhi, xlo, w1hi, w1lo, qkvp,
                                                  M_, 3 * D_, D_ / 2);
    }
    // 2) RoPE + split (Q in exp2 domain)
    {
        int total = BH_ * S_ * 32;
        rope_split_kernel<<<total / 256, 256>>>();
    }
    // 2b) V transpose + split
    {
        dim3 grid(S_ / 64, BH_);
        vtrans_kernel<<<grid, 256>>>();
    }
    // 3) Causal flash attention (fused epilogue split)
    {
        dim3 grid(S_ / 64, BH_);
        flash_mma_kernel<<<grid, 128, flash_smem>>>();
    }
    // 4) Output projection
    {
        dim3 grid(D_ / 128, M_ / 128);
        gemm_mma_kernel<<<grid, 256, gemm_smem>>>(athi, atlo, w2hi, w2lo, out,
                                                  M_, D_, D_ / 2);
    }
}

// round 14
// speedup vs baseline: 2.0235x; 1.0678x over previous
#include <cuda_runtime.h>
#include <cuda_bf16.h>
#include <math.h>
#include <float.h>
#include <stdint.h>

namespace {
constexpr int B_  = 2;
constexpr int S_  = 2048;
constexpr int D_  = 1024;
constexpr int H_  = 16;
constexpr int DH_ = 64;
constexpr int M_  = B_ * S_;          // 4096
constexpr int BH_ = B_ * H_;          // 32
}

// Scratch (device globals — allocation is forbidden)
__device__ float g_qkv[(size_t)M_ * 3 * D_];

__device__ uint32_t g_Xhi[(size_t)M_ * D_ / 2],  g_Xlo[(size_t)M_ * D_ / 2];
__device__ uint32_t g_W1hi[(size_t)3 * D_ * D_ / 2], g_W1lo[(size_t)3 * D_ * D_ / 2];
__device__ uint32_t g_W2hi[(size_t)D_ * D_ / 2], g_W2lo[(size_t)D_ * D_ / 2];
__device__ uint32_t g_AThi[(size_t)M_ * D_ / 2], g_ATlo[(size_t)M_ * D_ / 2];
__device__ uint32_t g_Qph[(size_t)BH_ * S_ * 32], g_Qpl[(size_t)BH_ * S_ * 32];
__device__ uint32_t g_Kph[(size_t)BH_ * S_ * 32], g_Kpl[(size_t)BH_ * S_ * 32];
__device__ uint32_t g_VTh[(size_t)BH_ * DH_ * (S_ / 2)], g_VTl[(size_t)BH_ * DH_ * (S_ / 2)];

// ---------------------------------------------------------------------------
__device__ __forceinline__ uint32_t smem_u32(const void* p) {
    uint32_t a;
    asm("{ .reg .u64 t; cvta.to.shared.u64 t, %1; cvt.u32.u64 %0, t; }"
        : "=r"(a) : "l"(p));
    return a;
}
__device__ __forceinline__ void split2(float a, float b, uint32_t& h, uint32_t& l)
{
    asm("cvt.rn.bf16x2.f32 %0, %1, %2;" : "=r"(h) : "f"(b), "f"(a));
    const float ha = __uint_as_float(h << 16);
    const float hb = __uint_as_float(h & 0xFFFF0000u);
    const float la = a - ha, lb = b - hb;
    asm("cvt.rn.bf16x2.f32 %0, %1, %2;" : "=r"(l) : "f"(lb), "f"(la));
}
__device__ __forceinline__ float ex2f(float x) {
    float y;
    asm("ex2.approx.f32 %0, %1;" : "=f"(y) : "f"(x));
    return y;
}

__global__ void convert_kernel(const float* __restrict__ src,
                               uint32_t* __restrict__ hi,
                               uint32_t* __restrict__ lo, int n4)
{
    int i = blockIdx.x * blockDim.x + threadIdx.x;
    if (i >= n4) return;
    float4 x = reinterpret_cast<const float4*>(src)[i];
    uint2 h, l;
    split2(x.x, x.y, h.x, l.x);
    split2(x.z, x.w, h.y, l.y);
    reinterpret_cast<uint2*>(hi)[i] = h;
    reinterpret_cast<uint2*>(lo)[i] = l;
}

__device__ __forceinline__ void mma_bf16(float c[4], const uint32_t a[4],
                                         uint32_t b0, uint32_t b1)
{
    asm volatile(
        "mma.sync.aligned.m16n8k16.row.col.f32.bf16.bf16.f32 "
        "{%0,%1,%2,%3}, {%4,%5,%6,%7}, {%8,%9}, {%0,%1,%2,%3};"
        : "+f"(c[0]), "+f"(c[1]), "+f"(c[2]), "+f"(c[3])
        : "r"(a[0]), "r"(a[1]), "r"(a[2]), "r"(a[3]), "r"(b0), "r"(b1));
}
__device__ __forceinline__ void ldsm_x4(uint32_t& r0, uint32_t& r1,
                                        uint32_t& r2, uint32_t& r3, uint32_t addr)
{
    asm volatile("ldmatrix.sync.aligned.m8n8.x4.shared.b16 {%0,%1,%2,%3}, [%4];"
                 : "=r"(r0), "=r"(r1), "=r"(r2), "=r"(r3) : "r"(addr));
}
#define CP16(sa, gp) \
    asm volatile("cp.async.cg.shared.global [%0], [%1], 16;" :: "r"(sa), "l"(gp))
#define CP_COMMIT() asm volatile("cp.async.commit_group;" ::: "memory")
#define CP_WAIT(n)  asm volatile("cp.async.wait_group %0;" :: "n"(n) : "memory")

// ---------------------------------------------------------------------------
// GEMM-NT, bf16x3 mma (best measured config, unchanged).
// ---------------------------------------------------------------------------
__global__ __launch_bounds__(256, 2)
void gemm_mma_kernel(const uint32_t* __restrict__ Ahi, const uint32_t* __restrict__ Alo,
                     const uint32_t* __restrict__ Bhi, const uint32_t* __restrict__ Blo,
                     float* __restrict__ C, int M, int N, int K2)
{
    constexpr int PAD = 20;
    constexpr int BUF = 128 * PAD * 4;
    constexpr int STG = 4 * BUF;
    extern __shared__ uint32_t dsm[];
    const uint32_t sbase = smem_u32(dsm);

    const int tid  = threadIdx.x;
    const int lane = tid & 31;
    const int wid  = tid >> 5;
    const int wm   = wid & 3;
    const int wn   = wid >> 2;
    const int bm   = blockIdx.y * 128;
    const int bn   = blockIdx.x * 128;

    const int cr = tid >> 2;
    const int cj = (tid & 3) << 2;
    const int arow = lane & 15;
    const int asel = ((lane >> 4) << 2);
    const int brow = (lane & 7) + ((lane >> 4) << 3);
    const int bsel = (((lane >> 3) & 1) << 2);

    float c[2][8][4];
#pragma unroll
    for (int mi = 0; mi < 2; mi++)
#pragma unroll
        for (int nj = 0; nj < 8; nj++)
#pragma unroll
            for (int k = 0; k < 4; k++) c[mi][nj][k] = 0.f;

    auto issue = [&](int cc, int stage) {
        const int kp = cc << 4;
        const uint32_t so = sbase + stage * STG;
        const size_t ga0 = (size_t)(bm + cr) * K2 + kp + cj;
        const size_t ga1 = (size_t)(bm + cr + 64) * K2 + kp + cj;
        const size_t gb0 = (size_t)(bn + cr) * K2 + kp + cj;
        const size_t gb1 = (size_t)(bn + cr + 64) * K2 + kp + cj;
        const uint32_t d0 = (uint32_t)(cr * PAD + cj) * 4;
        const uint32_t d1 = (uint32_t)((cr + 64) * PAD + cj) * 4;
        CP16(so + d0,           Ahi + ga0);  CP16(so + d1,           Ahi + ga1);
        CP16(so + BUF + d0,     Alo + ga0);  CP16(so + BUF + d1,     Alo + ga1);
        CP16(so + 2 * BUF + d0, Bhi + gb0);  CP16(so + 2 * BUF + d1, Bhi + gb1);
        CP16(so + 3 * BUF + d0, Blo + gb0);  CP16(so + 3 * BUF + d1, Blo + gb1);
        CP_COMMIT();
    };

    auto compute = [&](int stage) {
        const uint32_t so = sbase + stage * STG;
#pragma unroll
        for (int step = 0; step < 2; step++) {
            const int ko = step << 3;
            uint32_t aH[2][4], aL[2][4];
#pragma unroll
            for (int mi = 0; mi < 2; mi++) {
                const uint32_t ra = so +
                    (uint32_t)((wm * 32 + mi * 16 + arow) * PAD + ko + asel) * 4;
                ldsm_x4(aH[mi][0], aH[mi][1], aH[mi][2], aH[mi][3], ra);
                ldsm_x4(aL[mi][0], aL[mi][1], aL[mi][2], aL[mi][3], ra + BUF);
            }
#pragma unroll
            for (int nj2 = 0; nj2 < 4; nj2++) {
                const uint32_t rb = so + 2 * BUF +
                    (uint32_t)((wn * 64 + nj2 * 16 + brow) * PAD + ko + bsel) * 4;
                uint32_t bh[4], bl[4];
                ldsm_x4(bh[0], bh[1], bh[2], bh[3], rb);
                ldsm_x4(bl[0], bl[1], bl[2], bl[3], rb + BUF);
                mma_bf16(c[0][2 * nj2],     aH[0], bh[0], bh[1]);
                mma_bf16(c[1][2 * nj2],     aH[1], bh[0], bh[1]);
                mma_bf16(c[0][2 * nj2 + 1], aH[0], bh[2], bh[3]);
                mma_bf16(c[1][2 * nj2 + 1], aH[1], bh[2], bh[3]);
                mma_bf16(c[0][2 * nj2],     aH[0], bl[0], bl[1]);
                mma_bf16(c[1][2 * nj2],     aH[1], bl[0], bl[1]);
                mma_bf16(c[0][2 * nj2 + 1], aH[0], bl[2], bl[3]);
                mma_bf16(c[1][2 * nj2 + 1], aH[1], bl[2], bl[3]);
                mma_bf16(c[0][2 * nj2],     aL[0], bh[0], bh[1]);
                mma_bf16(c[1][2 * nj2],     aL[1], bh[0], bh[1]);
                mma_bf16(c[0][2 * nj2 + 1], aL[0], bh[2], bh[3]);
                mma_bf16(c[1][2 * nj2 + 1], aL[1], bh[2], bh[3]);
            }
        }
    };

    const int nchunks = K2 >> 4;
    issue(0, 0);
    for (int cc = 0; cc < nchunks; cc++) {
        CP_WAIT(0);
        __syncthreads();
        if (cc + 1 < nchunks) issue(cc + 1, (cc + 1) & 1);
        compute(cc & 1);
    }

    const int g = lane >> 2, t = lane & 3;
#pragma unroll
    for (int mi = 0; mi < 2; mi++) {
        const int row = bm + wm * 32 + mi * 16 + g;
#pragma unroll
        for (int nj = 0; nj < 8; nj++) {
            const int col = bn + wn * 64 + nj * 8 + 2 * t;
            *reinterpret_cast<float2*>(C + (size_t)row * N + col) =
                make_float2(c[mi][nj][0], c[mi][nj][1]);
            *reinterpret_cast<float2*>(C + (size_t)(row + 8) * N + col) =
                make_float2(c[mi][nj][2], c[mi][nj][3]);
        }
    }
}

// ---------------------------------------------------------------------------
// RoPE + split, s-pair version. Each thread handles (bh, s-pair, dh-pair):
// writes packed Q (exp2-scaled) / K, AND the transposed split V directly
// (VT pairs run along s, which the s-pair gives us in-thread).
// Replaces the old rope + vtrans kernels; V arithmetic identical.
// ---------------------------------------------------------------------------
__global__ void rope_split_kernel()
{
    int idx = blockIdx.x * blockDim.x + threadIdx.x;
    if (idx >= BH_ * (S_ / 2) * 32) return;
    const int p  = idx & 31;
    int t = idx >> 5;
    const int sp = t & (S_ / 2 - 1);
    t >>= 10;
    const int h = t & (H_ - 1);
    const int b = t >> 4;
    const int bh = b * H_ + h;
    const int s0 = 2 * sp, s1 = 2 * sp + 1;

    const double invf = exp(-9.210340371976184 * (double)(2 * p) / 64.0);
    double sd0, cd0, sd1, cd1;
    sincos((double)s0 * invf, &sd0, &cd0);
    sincos((double)s1 * invf, &sd1, &cd1);
    const float c0 = (float)cd0, n0 = (float)sd0;
    const float c1 = (float)cd1, n1 = (float)sd1;

    const float QSCALE = 0.18033688011112042f;   // 0.125 * log2(e)
    uint32_t h32, l32;

    const size_t row0 = (size_t)(b * S_ + s0) * (3 * D_) + h * DH_;
    const size_t row1 = (size_t)(b * S_ + s1) * (3 * D_) + h * DH_;
    const size_t po0  = ((size_t)bh * S_ + s0) * 32 + p;
    const size_t po1  = ((size_t)bh * S_ + s1) * 32 + p;

    {   // s0: Q, K
        const float qe = g_qkv[row0 + 2 * p],      qo = g_qkv[row0 + 2 * p + 1];
        const float ke = g_qkv[row0 + D_ + 2 * p], ko = g_qkv[row0 + D_ + 2 * p + 1];
        split2(QSCALE * (qe * c0 - qo * n0), QSCALE * (qe * n0 + qo * c0), h32, l32);
        g_Qph[po0] = h32; g_Qpl[po0] = l32;
        split2(ke * c0 - ko * n0, ke * n0 + ko * c0, h32, l32);
        g_Kph[po0] = h32; g_Kpl[po0] = l32;
    }
    {   // s1: Q, K
        const float qe = g_qkv[row1 + 2 * p],      qo = g_qkv[row1 + 2 * p + 1];
        const float ke = g_qkv[row1 + D_ + 2 * p], ko = g_qkv[row1 + D_ + 2 * p + 1];
        split2(QSCALE * (qe * c1 - qo * n1), QSCALE * (qe * n1 + qo * c1), h32, l32);
        g_Qph[po1] = h32; g_Qpl[po1] = l32;
        split2(ke * c1 - ko * n1, ke * n1 + ko * c1, h32, l32);
        g_Kph[po1] = h32; g_Kpl[po1] = l32;
    }
    {   // V transposed: pairs along s for dims d=2p and d=2p+1
        const float ve0 = g_qkv[row0 + 2 * D_ + 2 * p];
        const float vo0 = g_qkv[row0 + 2 * D_ + 2 * p + 1];
        const float ve1 = g_qkv[row1 + 2 * D_ + 2 * p];
        const float vo1 = g_qkv[row1 + 2 * D_ + 2 * p + 1];
        const size_t de = ((size_t)bh * DH_ + 2 * p) * (S_ / 2) + sp;
        const size_t dos = ((size_t)bh * DH_ + 2 * p + 1) * (S_ / 2) + sp;
        split2(ve0, ve1, h32, l32);
        g_VTh[de] = h32; g_VTl[de] = l32;
        split2(vo0, vo1, h32, l32);
        g_VTh[dos] = h32; g_VTl[dos] = l32;
    }
}

// ---------------------------------------------------------------------------
// Causal flash attention, bf16x3 mma, exp2-domain softmax, deferred l
// reduction, fused bf16-split epilogue. 3 CTAs/SM (reg cap 170) for
// latency hiding of the per-warp QK->softmax->PV chain.
// ---------------------------------------------------------------------------
__global__ __launch_bounds__(128, 3)
void flash_mma_kernel()
{
    constexpr int TBUF = 64 * 36 * 4;
    constexpr int TSTG = 4 * TBUF;
    extern __shared__ uint32_t fsm[];
    const uint32_t sbase = smem_u32(fsm);

    const int tid  = threadIdx.x;
    const int lane = tid & 31;
    const int warp = tid >> 5;
    const int g    = lane >> 2;
    const int t    = lane & 3;
    const int qb   = gridDim.x - 1 - blockIdx.x;
    const int bh   = blockIdx.y;
    const int q0   = qb * 64 + warp * 16;

    const int brow = (lane & 7) + ((lane >> 4) << 3);
    const int bsel = (((lane >> 3) & 1) << 2);

    const uint32_t* kh_g = g_Kph + (size_t)bh * S_ * 32;
    const uint32_t* kl_g = g_Kpl + (size_t)bh * S_ * 32;
    const uint32_t* vh_g = g_VTh + (size_t)bh * DH_ * (S_ / 2);
    const uint32_t* vl_g = g_VTl + (size_t)bh * DH_ * (S_ / 2);

    auto issue = [&](int kb, int stage) {
        const uint32_t so = sbase + stage * TSTG;
        const uint32_t* kh = kh_g + (size_t)(kb * 64) * 32;
        const uint32_t* kl = kl_g + (size_t)(kb * 64) * 32;
        const uint32_t* vh = vh_g + kb * 32;
        const uint32_t* vl = vl_g + kb * 32;
#pragma unroll
        for (int i = 0; i < 4; i++) {
            const int v = tid + i * 128;
            const int r = v >> 3;
            const int j = (v & 7) * 4;
            const uint32_t dd = (uint32_t)(r * 36 + j) * 4;
            CP16(so + dd,            kh + r * 32 + j);
            CP16(so + TBUF + dd,     kl + r * 32 + j);
            CP16(so + 2 * TBUF + dd, vh + r * (S_ / 2) + j);
            CP16(so + 3 * TBUF + dd, vl + r * (S_ / 2) + j);
        }
        CP_COMMIT();
    };

    // Q fragments
    uint32_t qh[4][4], ql[4][4];
    {
        const uint32_t* qp = g_Qph + ((size_t)bh * S_ + q0) * 32;
        const uint32_t* qq = g_Qpl + ((size_t)bh * S_ + q0) * 32;
#pragma unroll
        for (int d = 0; d < 4; d++) {
            const int c0 = 8 * d + t;
            qh[d][0] = qp[g * 32 + c0];        qh[d][1] = qp[(g + 8) * 32 + c0];
            qh[d][2] = qp[g * 32 + c0 + 4];    qh[d][3] = qp[(g + 8) * 32 + c0 + 4];
            ql[d][0] = qq[g * 32 + c0];        ql[d][1] = qq[(g + 8) * 32 + c0];
            ql[d][2] = qq[g * 32 + c0 + 4];    ql[d][3] = qq[(g + 8) * 32 + c0 + 4];
        }
    }

    float oc[8][4];
#pragma unroll
    for (int nj = 0; nj < 8; nj++)
#pragma unroll
        for (int k = 0; k < 4; k++) oc[nj][k] = 0.f;
    float m0 = -1e30f, m1 = -1e30f, l0 = 0.f, l1 = 0.f;

    issue(0, 0);
    for (int kb = 0; kb <= qb; kb++) {
        CP_WAIT(0);
        __syncthreads();
        if (kb < qb) issue(kb + 1, (kb + 1) & 1);

        const uint32_t so = sbase + (kb & 1) * TSTG;

        // ---- S = Q K^T ----
        float sc[8][4];
#pragma unroll
        for (int nj = 0; nj < 8; nj++)
#pragma unroll
            for (int k = 0; k < 4; k++) sc[nj][k] = 0.f;

#pragma unroll
        for (int d = 0; d < 4; d++) {
#pragma unroll
            for (int nj2 = 0; nj2 < 4; nj2++) {
                const uint32_t off = so +
                    (uint32_t)((nj2 * 16 + brow) * 36 + 8 * d + bsel) * 4;
                uint32_t kh4[4], kl4[4];
                ldsm_x4(kh4[0], kh4[1], kh4[2], kh4[3], off);
                ldsm_x4(kl4[0], kl4[1], kl4[2], kl4[3], off + TBUF);
                mma_bf16(sc[2 * nj2],     qh[d], kh4[0], kh4[1]);
                mma_bf16(sc[2 * nj2 + 1], qh[d], kh4[2], kh4[3]);
                mma_bf16(sc[2 * nj2],     qh[d], kl4[0], kl4[1]);
                mma_bf16(sc[2 * nj2 + 1], qh[d], kl4[2], kl4[3]);
                mma_bf16(sc[2 * nj2],     ql[d], kh4[0], kh4[1]);
                mma_bf16(sc[2 * nj2 + 1], ql[d], kh4[2], kh4[3]);
            }
        }

        if (kb == qb) {
            const int r0 = warp * 16 + g, r1 = r0 + 8;
#pragma unroll
            for (int nj = 0; nj < 8; nj++) {
                const int col = nj * 8 + 2 * t;
                if (col > r0)     sc[nj][0] = -1e30f;
                if (col + 1 > r0) sc[nj][1] = -1e30f;
                if (col > r1)     sc[nj][2] = -1e30f;
                if (col + 1 > r1) sc[nj][3] = -1e30f;
            }
        }

        // ---- softmax (exp2 domain) ----
        float rm0 = -1e30f, rm1 = -1e30f;
#pragma unroll
        for (int nj = 0; nj < 8; nj++) {
            rm0 = fmaxf(rm0, fmaxf(sc[nj][0], sc[nj][1]));
            rm1 = fmaxf(rm1, fmaxf(sc[nj][2], sc[nj][3]));
        }
        rm0 = fmaxf(rm0, __shfl_xor_sync(0xffffffffu, rm0, 1));
        rm0 = fmaxf(rm0, __shfl_xor_sync(0xffffffffu, rm0, 2));
        rm1 = fmaxf(rm1, __shfl_xor_sync(0xffffffffu, rm1, 1));
        rm1 = fmaxf(rm1, __shfl_xor_sync(0xffffffffu, rm1, 2));

        const float nm0 = fmaxf(m0, rm0), nm1 = fmaxf(m1, rm1);
        const float corr0 = ex2f(m0 - nm0), corr1 = ex2f(m1 - nm1);
        m0 = nm0; m1 = nm1;

        float rs0 = 0.f, rs1 = 0.f;
#pragma unroll
        for (int nj = 0; nj < 8; nj++) {
            sc[nj][0] = ex2f(sc[nj][0] - m0);
            sc[nj][1] = ex2f(sc[nj][1] - m0);
            sc[nj][2] = ex2f(sc[nj][2] - m1);
            sc[nj][3] = ex2f(sc[nj][3] - m1);
            rs0 += sc[nj][0] + sc[nj][1];
            rs1 += sc[nj][2] + sc[nj][3];
        }
        l0 = l0 * corr0 + rs0;
        l1 = l1 * corr1 + rs1;

#pragma unroll
        for (int nj = 0; nj < 8; nj++) {
            oc[nj][0] *= corr0; oc[nj][1] *= corr0;
            oc[nj][2] *= corr1; oc[nj][3] *= corr1;
        }

        // ---- O += P V ----
#pragma unroll
        for (int s = 0; s < 4; s++) {
            uint32_t ph[4], pl[4];
            split2(sc[2 * s][0],     sc[2 * s][1],     ph[0], pl[0]);
            split2(sc[2 * s][2],     sc[2 * s][3],     ph[1], pl[1]);
            split2(sc[2 * s + 1][0], sc[2 * s + 1][1], ph[2], pl[2]);
            split2(sc[2 * s + 1][2], sc[2 * s + 1][3], ph[3], pl[3]);
#pragma unroll
            for (int nj2 = 0; nj2 < 4; nj2++) {
                const uint32_t off = so + 2 * TBUF +
                    (uint32_t)((nj2 * 16 + brow) * 36 + 8 * s + bsel) * 4;
                uint32_t vh4[4], vl4[4];
                ldsm_x4(vh4[0], vh4[1], vh4[2], vh4[3], off);
                ldsm_x4(vl4[0], vl4[1], vl4[2], vl4[3], off + TBUF);
                mma_bf16(oc[2 * nj2],     ph, vh4[0], vh4[1]);
                mma_bf16(oc[2 * nj2 + 1], ph, vh4[2], vh4[3]);
                mma_bf16(oc[2 * nj2],     ph, vl4[0], vl4[1]);
                mma_bf16(oc[2 * nj2 + 1], ph, vl4[2], vl4[3]);
                mma_bf16(oc[2 * nj2],     pl, vh4[0], vh4[1]);
                mma_bf16(oc[2 * nj2 + 1], pl, vh4[2], vh4[3]);
            }
        }
    }

    // epilogue: reduce l, normalize, bf16-split directly into proj operand
    l0 += __shfl_xor_sync(0xffffffffu, l0, 1);
    l0 += __shfl_xor_sync(0xffffffffu, l0, 2);
    l1 += __shfl_xor_sync(0xffffffffu, l1, 1);
    l1 += __shfl_xor_sync(0xffffffffu, l1, 2);
    const float inv0 = 1.f / l0, inv1 = 1.f / l1;
    const int b = bh >> 4, h = bh & 15;
    const int r0 = q0 + g, r1 = r0 + 8;
#pragma unroll
    for (int nj = 0; nj < 8; nj++) {
        const size_t p0 = (size_t)(b * S_ + r0) * (D_ / 2) + h * 32 + nj * 4 + t;
        const size_t p1 = (size_t)(b * S_ + r1) * (D_ / 2) + h * 32 + nj * 4 + t;
        uint32_t hh, ll;
        split2(oc[nj][0] * inv0, oc[nj][1] * inv0, hh, ll);
        g_AThi[p0] = hh; g_ATlo[p0] = ll;
        split2(oc[nj][2] * inv1, oc[nj][3] * inv1, hh, ll);
        g_AThi[p1] = hh; g_ATlo[p1] = ll;
    }
}

// ---------------------------------------------------------------------------
extern "C" void kernel_launch(void* const* d_in, const int* in_sizes, int n_in,
                              void* d_out, int out_size)
{
    const float* X    = (const float*)d_in[0];
    const float* Wqkv = (const float*)d_in[1];
    const float* Wo   = (const float*)d_in[2];
    float* out = (float*)d_out;
    (void)in_sizes; (void)n_in; (void)out_size;

    float* qkvp = nullptr;
    cudaGetSymbolAddress((void**)&qkvp, g_qkv);
    uint32_t *xhi, *xlo, *w1hi, *w1lo, *w2hi, *w2lo, *athi, *atlo;
    cudaGetSymbolAddress((void**)&xhi,  g_Xhi);
    cudaGetSymbolAddress((void**)&xlo,  g_Xlo);
    cudaGetSymbolAddress((void**)&w1hi, g_W1hi);
    cudaGetSymbolAddress((void**)&w1lo, g_W1lo);
    cudaGetSymbolAddress((void**)&w2hi, g_W2hi);
    cudaGetSymbolAddress((void**)&w2lo, g_W2lo);
    cudaGetSymbolAddress((void**)&athi, g_AThi);
    cudaGetSymbolAddress((void**)&atlo, g_ATlo);

    const int gemm_smem  = 2 * 4 * 128 * 20 * 4;   // 81920
    const int flash_smem = 2 * 4 * 64 * 36 * 4;    // 73728
    cudaFuncSetAttribute(gemm_mma_kernel,
                         cudaFuncAttributeMaxDynamicSharedMemorySize, gemm_smem);
    cudaFuncSetAttribute(flash_mma_kernel,
                         cudaFuncAttributeMaxDynamicSharedMemorySize, flash_smem);

    // 0) Split inputs into bf16 hi/lo
    {
        int n4 = M_ * D_ / 4;
        convert_kernel<<<n4 / 256, 256>>>(X, xhi, xlo, n4);
        n4 = 3 * D_ * D_ / 4;
        convert_kernel<<<n4 / 256, 256>>>(Wqkv, w1hi, w1lo, n4);
        n4 = D_ * D_ / 4;
        convert_kernel<<<n4 / 256, 256>>>(Wo, w2hi, w2lo, n4);
    }
    // 1) QKV projection
    {
        dim3 grid(3 * D_ / 128, M_ / 128);
        gemm_mma_kernel<<<grid, 256, gemm_smem>>>(xhi, xlo, w1hi, w1lo, qkvp,
                                                  M_, 3 * D_, D_ / 2);
    }
    // 2) RoPE + split + transposed V (vtrans fused)
    {
        int total = BH_ * (S_ / 2) * 32;           // 1,048,576
        rope_split_kernel<<<total / 256, 256>>>();
    }
    // 3) Causal flash attention (fused epilogue split)
    {
        dim3 grid(S_ / 64, BH_);
        flash_mma_kernel<<<grid, 128, flash_smem>>>();
    }
    // 4) Output projection
    {
        dim3 grid(D_ / 128, M_ / 128);
        gemm_mma_kernel<<<grid, 256, gemm_smem>>>(athi, atlo, w2hi, w2lo, out,
                                                  M_, D_, D_ / 2);
    }
}

// round 15
// speedup vs baseline: 2.3744x; 1.1734x over previous
#include <cuda_runtime.h>
#include <cuda_bf16.h>
#include <math.h>
#include <float.h>
#include <stdint.h>

namespace {
constexpr int B_  = 2;
constexpr int S_  = 2048;
constexpr int D_  = 1024;
constexpr int H_  = 16;
constexpr int DH_ = 64;
constexpr int M_  = B_ * S_;          // 4096
constexpr int BH_ = B_ * H_;          // 32
}

// Scratch (device globals — allocation is forbidden)
__device__ float g_qkv[(size_t)M_ * 3 * D_];

__device__ uint32_t g_Xhi[(size_t)M_ * D_ / 2],  g_Xlo[(size_t)M_ * D_ / 2];
__device__ uint32_t g_W1hi[(size_t)3 * D_ * D_ / 2], g_W1lo[(size_t)3 * D_ * D_ / 2];
__device__ uint32_t g_W2hi[(size_t)D_ * D_ / 2], g_W2lo[(size_t)D_ * D_ / 2];
__device__ uint32_t g_AThi[(size_t)M_ * D_ / 2], g_ATlo[(size_t)M_ * D_ / 2];
__device__ uint32_t g_Qph[(size_t)BH_ * S_ * 32], g_Qpl[(size_t)BH_ * S_ * 32];
__device__ uint32_t g_Kph[(size_t)BH_ * S_ * 32], g_Kpl[(size_t)BH_ * S_ * 32];
__device__ uint32_t g_VTh[(size_t)BH_ * DH_ * (S_ / 2)], g_VTl[(size_t)BH_ * DH_ * (S_ / 2)];

// ---------------------------------------------------------------------------
__device__ __forceinline__ uint32_t smem_u32(const void* p) {
    uint32_t a;
    asm("{ .reg .u64 t; cvta.to.shared.u64 t, %1; cvt.u32.u64 %0, t; }"
        : "=r"(a) : "l"(p));
    return a;
}
__device__ __forceinline__ void split2(float a, float b, uint32_t& h, uint32_t& l)
{
    asm("cvt.rn.bf16x2.f32 %0, %1, %2;" : "=r"(h) : "f"(b), "f"(a));
    const float ha = __uint_as_float(h << 16);
    const float hb = __uint_as_float(h & 0xFFFF0000u);
    const float la = a - ha, lb = b - hb;
    asm("cvt.rn.bf16x2.f32 %0, %1, %2;" : "=r"(l) : "f"(lb), "f"(la));
}
__device__ __forceinline__ float ex2f(float x) {
    float y;
    asm("ex2.approx.f32 %0, %1;" : "=f"(y) : "f"(x));
    return y;
}

__global__ void convert_kernel(const float* __restrict__ src,
                               uint32_t* __restrict__ hi,
                               uint32_t* __restrict__ lo, int n4)
{
    int i = blockIdx.x * blockDim.x + threadIdx.x;
    if (i >= n4) return;
    float4 x = reinterpret_cast<const float4*>(src)[i];
    uint2 h, l;
    split2(x.x, x.y, h.x, l.x);
    split2(x.z, x.w, h.y, l.y);
    reinterpret_cast<uint2*>(hi)[i] = h;
    reinterpret_cast<uint2*>(lo)[i] = l;
}

__device__ __forceinline__ void mma_bf16(float c[4], const uint32_t a[4],
                                         uint32_t b0, uint32_t b1)
{
    asm volatile(
        "mma.sync.aligned.m16n8k16.row.col.f32.bf16.bf16.f32 "
        "{%0,%1,%2,%3}, {%4,%5,%6,%7}, {%8,%9}, {%0,%1,%2,%3};"
        : "+f"(c[0]), "+f"(c[1]), "+f"(c[2]), "+f"(c[3])
        : "r"(a[0]), "r"(a[1]), "r"(a[2]), "r"(a[3]), "r"(b0), "r"(b1));
}
__device__ __forceinline__ void ldsm_x4(uint32_t& r0, uint32_t& r1,
                                        uint32_t& r2, uint32_t& r3, uint32_t addr)
{
    asm volatile("ldmatrix.sync.aligned.m8n8.x4.shared.b16 {%0,%1,%2,%3}, [%4];"
                 : "=r"(r0), "=r"(r1), "=r"(r2), "=r"(r3) : "r"(addr));
}
#define CP16(sa, gp) \
    asm volatile("cp.async.cg.shared.global [%0], [%1], 16;" :: "r"(sa), "l"(gp))
#define CP_COMMIT() asm volatile("cp.async.commit_group;" ::: "memory")
#define CP_WAIT(n)  asm volatile("cp.async.wait_group %0;" :: "n"(n) : "memory")

// ---------------------------------------------------------------------------
// GEMM-NT, bf16x3 mma. mi-outer compute: only one mi's a-fragments live at a
// time (register-pressure relief; b-frags re-loaded per mi — LDSM is cheap).
// Per-accumulator term order unchanged (hi*hi, hi*lo, lo*hi) => bit-identical.
// ---------------------------------------------------------------------------
__global__ __launch_bounds__(256, 2)
void gemm_mma_kernel(const uint32_t* __restrict__ Ahi, const uint32_t* __restrict__ Alo,
                     const uint32_t* __restrict__ Bhi, const uint32_t* __restrict__ Blo,
                     float* __restrict__ C, int M, int N, int K2)
{
    constexpr int PAD = 20;
    constexpr int BUF = 128 * PAD * 4;
    constexpr int STG = 4 * BUF;
    extern __shared__ uint32_t dsm[];
    const uint32_t sbase = smem_u32(dsm);

    const int tid  = threadIdx.x;
    const int lane = tid & 31;
    const int wid  = tid >> 5;
    const int wm   = wid & 3;
    const int wn   = wid >> 2;
    const int bm   = blockIdx.y * 128;
    const int bn   = blockIdx.x * 128;

    const int cr = tid >> 2;
    const int cj = (tid & 3) << 2;
    const int arow = lane & 15;
    const int asel = ((lane >> 4) << 2);
    const int brow = (lane & 7) + ((lane >> 4) << 3);
    const int bsel = (((lane >> 3) & 1) << 2);

    float c[2][8][4];
#pragma unroll
    for (int mi = 0; mi < 2; mi++)
#pragma unroll
        for (int nj = 0; nj < 8; nj++)
#pragma unroll
            for (int k = 0; k < 4; k++) c[mi][nj][k] = 0.f;

    auto issue = [&](int cc, int stage) {
        const int kp = cc << 4;
        const uint32_t so = sbase + stage * STG;
        const size_t ga0 = (size_t)(bm + cr) * K2 + kp + cj;
        const size_t ga1 = (size_t)(bm + cr + 64) * K2 + kp + cj;
        const size_t gb0 = (size_t)(bn + cr) * K2 + kp + cj;
        const size_t gb1 = (size_t)(bn + cr + 64) * K2 + kp + cj;
        const uint32_t d0 = (uint32_t)(cr * PAD + cj) * 4;
        const uint32_t d1 = (uint32_t)((cr + 64) * PAD + cj) * 4;
        CP16(so + d0,           Ahi + ga0);  CP16(so + d1,           Ahi + ga1);
        CP16(so + BUF + d0,     Alo + ga0);  CP16(so + BUF + d1,     Alo + ga1);
        CP16(so + 2 * BUF + d0, Bhi + gb0);  CP16(so + 2 * BUF + d1, Bhi + gb1);
        CP16(so + 3 * BUF + d0, Blo + gb0);  CP16(so + 3 * BUF + d1, Blo + gb1);
        CP_COMMIT();
    };

    auto compute = [&](int stage) {
        const uint32_t so = sbase + stage * STG;
#pragma unroll
        for (int step = 0; step < 2; step++) {
            const int ko = step << 3;
#pragma unroll
            for (int mi = 0; mi < 2; mi++) {
                uint32_t aH[4], aL[4];
                const uint32_t ra = so +
                    (uint32_t)((wm * 32 + mi * 16 + arow) * PAD + ko + asel) * 4;
                ldsm_x4(aH[0], aH[1], aH[2], aH[3], ra);
                ldsm_x4(aL[0], aL[1], aL[2], aL[3], ra + BUF);
#pragma unroll
                for (int nj2 = 0; nj2 < 4; nj2++) {
                    const uint32_t rb = so + 2 * BUF +
                        (uint32_t)((wn * 64 + nj2 * 16 + brow) * PAD + ko + bsel) * 4;
                    uint32_t bh[4], bl[4];
                    ldsm_x4(bh[0], bh[1], bh[2], bh[3], rb);
                    ldsm_x4(bl[0], bl[1], bl[2], bl[3], rb + BUF);
                    mma_bf16(c[mi][2 * nj2],     aH, bh[0], bh[1]);
                    mma_bf16(c[mi][2 * nj2 + 1], aH, bh[2], bh[3]);
                    mma_bf16(c[mi][2 * nj2],     aH, bl[0], bl[1]);
                    mma_bf16(c[mi][2 * nj2 + 1], aH, bl[2], bl[3]);
                    mma_bf16(c[mi][2 * nj2],     aL, bh[0], bh[1]);
                    mma_bf16(c[mi][2 * nj2 + 1], aL, bh[2], bh[3]);
                }
            }
        }
    };

    const int nchunks = K2 >> 4;
    issue(0, 0);
    for (int cc = 0; cc < nchunks; cc++) {
        CP_WAIT(0);
        __syncthreads();
        if (cc + 1 < nchunks) issue(cc + 1, (cc + 1) & 1);
        compute(cc & 1);
    }

    const int g = lane >> 2, t = lane & 3;
#pragma unroll
    for (int mi = 0; mi < 2; mi++) {
        const int row = bm + wm * 32 + mi * 16 + g;
#pragma unroll
        for (int nj = 0; nj < 8; nj++) {
            const int col = bn + wn * 64 + nj * 8 + 2 * t;
            *reinterpret_cast<float2*>(C + (size_t)row * N + col) =
                make_float2(c[mi][nj][0], c[mi][nj][1]);
            *reinterpret_cast<float2*>(C + (size_t)(row + 8) * N + col) =
                make_float2(c[mi][nj][2], c[mi][nj][3]);
        }
    }
}

// ---------------------------------------------------------------------------
// RoPE + split, s-pair version, fp32 sincosf (angle computed in double —
// reference itself rounds angles to fp32, same discrepancy class).
// ---------------------------------------------------------------------------
__global__ void rope_split_kernel()
{
    int idx = blockIdx.x * blockDim.x + threadIdx.x;
    if (idx >= BH_ * (S_ / 2) * 32) return;
    const int p  = idx & 31;
    int t = idx >> 5;
    const int sp = t & (S_ / 2 - 1);
    t >>= 10;
    const int h = t & (H_ - 1);
    const int b = t >> 4;
    const int bh = b * H_ + h;
    const int s0 = 2 * sp, s1 = 2 * sp + 1;

    const double invf = exp(-9.210340371976184 * (double)(2 * p) / 64.0);
    float n0, c0, n1, c1;
    sincosf((float)((double)s0 * invf), &n0, &c0);
    sincosf((float)((double)s1 * invf), &n1, &c1);

    const float QSCALE = 0.18033688011112042f;   // 0.125 * log2(e)
    uint32_t h32, l32;

    const size_t row0 = (size_t)(b * S_ + s0) * (3 * D_) + h * DH_;
    const size_t row1 = (size_t)(b * S_ + s1) * (3 * D_) + h * DH_;
    const size_t po0  = ((size_t)bh * S_ + s0) * 32 + p;
    const size_t po1  = ((size_t)bh * S_ + s1) * 32 + p;

    {   // s0: Q, K
        const float qe = g_qkv[row0 + 2 * p],      qo = g_qkv[row0 + 2 * p + 1];
        const float ke = g_qkv[row0 + D_ + 2 * p], ko = g_qkv[row0 + D_ + 2 * p + 1];
        split2(QSCALE * (qe * c0 - qo * n0), QSCALE * (qe * n0 + qo * c0), h32, l32);
        g_Qph[po0] = h32; g_Qpl[po0] = l32;
        split2(ke * c0 - ko * n0, ke * n0 + ko * c0, h32, l32);
        g_Kph[po0] = h32; g_Kpl[po0] = l32;
    }
    {   // s1: Q, K
        const float qe = g_qkv[row1 + 2 * p],      qo = g_qkv[row1 + 2 * p + 1];
        const float ke = g_qkv[row1 + D_ + 2 * p], ko = g_qkv[row1 + D_ + 2 * p + 1];
        split2(QSCALE * (qe * c1 - qo * n1), QSCALE * (qe * n1 + qo * c1), h32, l32);
        g_Qph[po1] = h32; g_Qpl[po1] = l32;
        split2(ke * c1 - ko * n1, ke * n1 + ko * c1, h32, l32);
        g_Kph[po1] = h32; g_Kpl[po1] = l32;
    }
    {   // V transposed: pairs along s for dims d=2p and d=2p+1
        const float ve0 = g_qkv[row0 + 2 * D_ + 2 * p];
        const float vo0 = g_qkv[row0 + 2 * D_ + 2 * p + 1];
        const float ve1 = g_qkv[row1 + 2 * D_ + 2 * p];
        const float vo1 = g_qkv[row1 + 2 * D_ + 2 * p + 1];
        const size_t de  = ((size_t)bh * DH_ + 2 * p) * (S_ / 2) + sp;
        const size_t dos = ((size_t)bh * DH_ + 2 * p + 1) * (S_ / 2) + sp;
        split2(ve0, ve1, h32, l32);
        g_VTh[de] = h32; g_VTl[de] = l32;
        split2(vo0, vo1, h32, l32);
        g_VTh[dos] = h32; g_VTl[dos] = l32;
    }
}

// ---------------------------------------------------------------------------
// Causal flash attention, bf16x3 mma, exp2-domain softmax, deferred l
// reduction, fused bf16-split epilogue, 3 CTAs/SM (R14 config, unchanged).
// ---------------------------------------------------------------------------
__global__ __launch_bounds__(128, 3)
void flash_mma_kernel()
{
    constexpr int TBUF = 64 * 36 * 4;
    constexpr int TSTG = 4 * TBUF;
    extern __shared__ uint32_t fsm[];
    const uint32_t sbase = smem_u32(fsm);

    const int tid  = threadIdx.x;
    const int lane = tid & 31;
    const int warp = tid >> 5;
    const int g    = lane >> 2;
    const int t    = lane & 3;
    const int qb   = gridDim.x - 1 - blockIdx.x;
    const int bh   = blockIdx.y;
    const int q0   = qb * 64 + warp * 16;

    const int brow = (lane & 7) + ((lane >> 4) << 3);
    const int bsel = (((lane >> 3) & 1) << 2);

    const uint32_t* kh_g = g_Kph + (size_t)bh * S_ * 32;
    const uint32_t* kl_g = g_Kpl + (size_t)bh * S_ * 32;
    const uint32_t* vh_g = g_VTh + (size_t)bh * DH_ * (S_ / 2);
    const uint32_t* vl_g = g_VTl + (size_t)bh * DH_ * (S_ / 2);

    auto issue = [&](int kb, int stage) {
        const uint32_t so = sbase + stage * TSTG;
        const uint32_t* kh = kh_g + (size_t)(kb * 64) * 32;
        const uint32_t* kl = kl_g + (size_t)(kb * 64) * 32;
        const uint32_t* vh = vh_g + kb * 32;
        const uint32_t* vl = vl_g + kb * 32;
#pragma unroll
        for (int i = 0; i < 4; i++) {
            const int v = tid + i * 128;
            const int r = v >> 3;
            const int j = (v & 7) * 4;
            const uint32_t dd = (uint32_t)(r * 36 + j) * 4;
            CP16(so + dd,            kh + r * 32 + j);
            CP16(so + TBUF + dd,     kl + r * 32 + j);
            CP16(so + 2 * TBUF + dd, vh + r * (S_ / 2) + j);
            CP16(so + 3 * TBUF + dd, vl + r * (S_ / 2) + j);
        }
        CP_COMMIT();
    };

    // Q fragments
    uint32_t qh[4][4], ql[4][4];
    {
        const uint32_t* qp = g_Qph + ((size_t)bh * S_ + q0) * 32;
        const uint32_t* qq = g_Qpl + ((size_t)bh * S_ + q0) * 32;
#pragma unroll
        for (int d = 0; d < 4; d++) {
            const int c0 = 8 * d + t;
            qh[d][0] = qp[g * 32 + c0];        qh[d][1] = qp[(g + 8) * 32 + c0];
            qh[d][2] = qp[g * 32 + c0 + 4];    qh[d][3] = qp[(g + 8) * 32 + c0 + 4];
            ql[d][0] = qq[g * 32 + c0];        ql[d][1] = qq[(g + 8) * 32 + c0];
            ql[d][2] = qq[g * 32 + c0 + 4];    ql[d][3] = qq[(g + 8) * 32 + c0 + 4];
        }
    }

    float oc[8][4];
#pragma unroll
    for (int nj = 0; nj < 8; nj++)
#pragma unroll
        for (int k = 0; k < 4; k++) oc[nj][k] = 0.f;
    float m0 = -1e30f, m1 = -1e30f, l0 = 0.f, l1 = 0.f;

    issue(0, 0);
    for (int kb = 0; kb <= qb; kb++) {
        CP_WAIT(0);
        __syncthreads();
        if (kb < qb) issue(kb + 1, (kb + 1) & 1);

        const uint32_t so = sbase + (kb & 1) * TSTG;

        // ---- S = Q K^T ----
        float sc[8][4];
#pragma unroll
        for (int nj = 0; nj < 8; nj++)
#pragma unroll
            for (int k = 0; k < 4; k++) sc[nj][k] = 0.f;

#pragma unroll
        for (int d = 0; d < 4; d++) {
#pragma unroll
            for (int nj2 = 0; nj2 < 4; nj2++) {
                const uint32_t off = so +
                    (uint32_t)((nj2 * 16 + brow) * 36 + 8 * d + bsel) * 4;
                uint32_t kh4[4], kl4[4];
                ldsm_x4(kh4[0], kh4[1], kh4[2], kh4[3], off);
                ldsm_x4(kl4[0], kl4[1], kl4[2], kl4[3], off + TBUF);
                mma_bf16(sc[2 * nj2],     qh[d], kh4[0], kh4[1]);
                mma_bf16(sc[2 * nj2 + 1], qh[d], kh4[2], kh4[3]);
                mma_bf16(sc[2 * nj2],     qh[d], kl4[0], kl4[1]);
                mma_bf16(sc[2 * nj2 + 1], qh[d], kl4[2], kl4[3]);
                mma_bf16(sc[2 * nj2],     ql[d], kh4[0], kh4[1]);
                mma_bf16(sc[2 * nj2 + 1], ql[d], kh4[2], kh4[3]);
            }
        }

        if (kb == qb) {
            const int r0 = warp * 16 + g, r1 = r0 + 8;
#pragma unroll
            for (int nj = 0; nj < 8; nj++) {
                const int col = nj * 8 + 2 * t;
                if (col > r0)     sc[nj][0] = -1e30f;
                if (col + 1 > r0) sc[nj][1] = -1e30f;
                if (col > r1)     sc[nj][2] = -1e30f;
                if (col + 1 > r1) sc[nj][3] = -1e30f;
            }
        }

        // ---- softmax (exp2 domain) ----
        float rm0 = -1e30f, rm1 = -1e30f;
#pragma unroll
        for (int nj = 0; nj < 8; nj++) {
            rm0 = fmaxf(rm0, fmaxf(sc[nj][0], sc[nj][1]));
            rm1 = fmaxf(rm1, fmaxf(sc[nj][2], sc[nj][3]));
        }
        rm0 = fmaxf(rm0, __shfl_xor_sync(0xffffffffu, rm0, 1));
        rm0 = fmaxf(rm0, __shfl_xor_sync(0xffffffffu, rm0, 2));
        rm1 = fmaxf(rm1, __shfl_xor_sync(0xffffffffu, rm1, 1));
        rm1 = fmaxf(rm1, __shfl_xor_sync(0xffffffffu, rm1, 2));

        const float nm0 = fmaxf(m0, rm0), nm1 = fmaxf(m1, rm1);
        const float corr0 = ex2f(m0 - nm0), corr1 = ex2f(m1 - nm1);
        m0 = nm0; m1 = nm1;

        float rs0 = 0.f, rs1 = 0.f;
#pragma unroll
        for (int nj = 0; nj < 8; nj++) {
            sc[nj][0] = ex2f(sc[nj][0] - m0);
            sc[nj][1] = ex2f(sc[nj][1] - m0);
            sc[nj][2] = ex2f(sc[nj][2] - m1);
            sc[nj][3] = ex2f(sc[nj][3] - m1);
            rs0 += sc[nj][0] + sc[nj][1];
            rs1 += sc[nj][2] + sc[nj][3];
        }
        l0 = l0 * corr0 + rs0;
        l1 = l1 * corr1 + rs1;

#pragma unroll
        for (int nj = 0; nj < 8; nj++) {
            oc[nj][0] *= corr0; oc[nj][1] *= corr0;
            oc[nj][2] *= corr1; oc[nj][3] *= corr1;
        }

        // ---- O += P V ----
#pragma unroll
        for (int s = 0; s < 4; s++) {
            uint32_t ph[4], pl[4];
            split2(sc[2 * s][0],     sc[2 * s][1],     ph[0], pl[0]);
            split2(sc[2 * s][2],     sc[2 * s][3],     ph[1], pl[1]);
            split2(sc[2 * s + 1][0], sc[2 * s + 1][1], ph[2], pl[2]);
            split2(sc[2 * s + 1][2], sc[2 * s + 1][3], ph[3], pl[3]);
#pragma unroll
            for (int nj2 = 0; nj2 < 4; nj2++) {
                const uint32_t off = so + 2 * TBUF +
                    (uint32_t)((nj2 * 16 + brow) * 36 + 8 * s + bsel) * 4;
                uint32_t vh4[4], vl4[4];
                ldsm_x4(vh4[0], vh4[1], vh4[2], vh4[3], off);
                ldsm_x4(vl4[0], vl4[1], vl4[2], vl4[3], off + TBUF);
                mma_bf16(oc[2 * nj2],     ph, vh4[0], vh4[1]);
                mma_bf16(oc[2 * nj2 + 1], ph, vh4[2], vh4[3]);
                mma_bf16(oc[2 * nj2],     ph, vl4[0], vl4[1]);
                mma_bf16(oc[2 * nj2 + 1], ph, vl4[2], vl4[3]);
                mma_bf16(oc[2 * nj2],     pl, vh4[0], vh4[1]);
                mma_bf16(oc[2 * nj2 + 1], pl, vh4[2], vh4[3]);
            }
        }
    }

    // epilogue: reduce l, normalize, bf16-split directly into proj operand
    l0 += __shfl_xor_sync(0xffffffffu, l0, 1);
    l0 += __shfl_xor_sync(0xffffffffu, l0, 2);
    l1 += __shfl_xor_sync(0xffffffffu, l1, 1);
    l1 += __shfl_xor_sync(0xffffffffu, l1, 2);
    const float inv0 = 1.f / l0, inv1 = 1.f / l1;
    const int b = bh >> 4, h = bh & 15;
    const int r0 = q0 + g, r1 = r0 + 8;
#pragma unroll
    for (int nj = 0; nj < 8; nj++) {
        const size_t p0 = (size_t)(b * S_ + r0) * (D_ / 2) + h * 32 + nj * 4 + t;
        const size_t p1 = (size_t)(b * S_ + r1) * (D_ / 2) + h * 32 + nj * 4 + t;
        uint32_t hh, ll;
        split2(oc[nj][0] * inv0, oc[nj][1] * inv0, hh, ll);
        g_AThi[p0] = hh; g_ATlo[p0] = ll;
        split2(oc[nj][2] * inv1, oc[nj][3] * inv1, hh, ll);
        g_AThi[p1] = hh; g_ATlo[p1] = ll;
    }
}

// ---------------------------------------------------------------------------
extern "C" void kernel_launch(void* const* d_in, const int* in_sizes, int n_in,
                              void* d_out, int out_size)
{
    const float* X    = (const float*)d_in[0];
    const float* Wqkv = (const float*)d_in[1];
    const float* Wo   = (const float*)d_in[2];
    float* out = (float*)d_out;
    (void)in_sizes; (void)n_in; (void)out_size;

    float* qkvp = nullptr;
    cudaGetSymbolAddress((void**)&qkvp, g_qkv);
    uint32_t *xhi, *xlo, *w1hi, *w1lo, *w2hi, *w2lo, *athi, *atlo;
    cudaGetSymbolAddress((void**)&xhi,  g_Xhi);
    cudaGetSymbolAddress((void**)&xlo,  g_Xlo);
    cudaGetSymbolAddress((void**)&w1hi, g_W1hi);
    cudaGetSymbolAddress((void**)&w1lo, g_W1lo);
    cudaGetSymbolAddress((void**)&w2hi, g_W2hi);
    cudaGetSymbolAddress((void**)&w2lo, g_W2lo);
    cudaGetSymbolAddress((void**)&athi, g_AThi);
    cudaGetSymbolAddress((void**)&atlo, g_ATlo);

    const int gemm_smem  = 2 * 4 * 128 * 20 * 4;   // 81920
    const int flash_smem = 2 * 4 * 64 * 36 * 4;    // 73728
    cudaFuncSetAttribute(gemm_mma_kernel,
                         cudaFuncAttributeMaxDynamicSharedMemorySize, gemm_smem);
    cudaFuncSetAttribute(flash_mma_kernel,
                         cudaFuncAttributeMaxDynamicSharedMemorySize, flash_smem);

    // 0) Split inputs into bf16 hi/lo
    {
        int n4 = M_ * D_ / 4;
        convert_kernel<<<n4 / 256, 256>>>(X, xhi, xlo, n4);
        n4 = 3 * D_ * D_ / 4;
        convert_kernel<<<n4 / 256, 256>>>(Wqkv, w1hi, w1lo, n4);
        n4 = D_ * D_ / 4;
        convert_kernel<<<n4 / 256, 256>>>(Wo, w2hi, w2lo, n4);
    }
    // 1) QKV projection
    {
        dim3 grid(3 * D_ / 128, M_ / 128);
        gemm_mma_kernel<<<grid, 256, gemm_smem>>>(xhi, xlo, w1hi, w1lo, qkvp,
                                                  M_, 3 * D_, D_ / 2);
    }
    // 2) RoPE + split + transposed V
    {
        int total = BH_ * (S_ / 2) * 32;           // 1,048,576
        rope_split_kernel<<<total / 256, 256>>>();
    }
    // 3) Causal flash attention (fused epilogue split)
    {
        dim3 grid(S_ / 64, BH_);
        flash_mma_kernel<<<grid, 128, flash_smem>>>();
    }
    // 4) Output projection
    {
        dim3 grid(D_ / 128, M_ / 128);
        gemm_mma_kernel<<<grid, 256, gemm_smem>>>(athi, atlo, w2hi, w2lo, out,
                                                  M_, D_, D_ / 2);
    }
}